// round 6
// baseline (speedup 1.0000x reference)
#include <cuda_runtime.h>
#include <cuda_bf16.h>
#include <math.h>
#include <stdint.h>

#define N      8192
#define INCH   256
#define OUTCH  64
#define NSPLIT 2
#define JSPAN  (N / NSPLIT)     // 4096
#define TIROWS 128
#define NH     (JSPAN / 32)     // 128 halves (32 j each)

// cp.async pipeline
#define STAGES     6
#define ADJ_PITCH  144                       // bytes per adj row in smem (conflict-free)
#define ADJ_BYTES  (TIROWS * ADJ_PITCH)      // 18432
#define STAGE_SZ   (ADJ_BYTES + 256)         // + ep tile (32 x float2)
#define SMEM_MAIN  (STAGES * STAGE_SZ)       // 112128

// ---------------- device scratch ----------------
__device__ float    g_Wh[N * OUTCH];
__device__ float    g_s1[N], g_s2[N];
__device__ unsigned g_m1u, g_m2u;                 // encoded float max (idempotent)
__device__ __align__(16) float2 g_ep2[N];         // (E1_j, Eh_j)
__device__ float2   g_ar2[N];                     // (A1_i, Ah_i)
// B in mma-fragment layout: [kbg 0..511][nt 0..7][lane 0..31] x uint4(b0hi,b1hi,b0lo,b1lo)
__device__ uint4    g_Bfrag[(N / 16) * 8 * 32];
__device__ float    g_part[NSPLIT * N * OUTCH];
__device__ float    g_Zp[NSPLIT * N];

__device__ __forceinline__ unsigned fenc(float f) {
    unsigned u = __float_as_uint(f);
    return (u & 0x80000000u) ? ~u : (u | 0x80000000u);
}
__device__ __forceinline__ float fdec(unsigned k) {
    return __uint_as_float((k & 0x80000000u) ? (k ^ 0x80000000u) : ~k);
}
__device__ __forceinline__ uint32_t bf16x2_pack(float lo, float hi) {
    uint32_t r;
    asm("cvt.rn.bf16x2.f32 %0, %1, %2;" : "=r"(r) : "f"(hi), "f"(lo));  // upper=hi, lower=lo
    return r;
}
__device__ __forceinline__ uint32_t smem_u32(const void* p) {
    uint32_t a;
    asm("{ .reg .u64 t; cvta.to.shared.u64 t, %1; cvt.u32.u64 %0, t; }" : "=r"(a) : "l"(p));
    return a;
}

#define MMA16816(d, a0, a1, a2, a3, b0, b1)                                       \
    asm volatile("mma.sync.aligned.m16n8k16.row.col.f32.bf16.bf16.f32 "          \
        "{%0,%1,%2,%3}, {%4,%5,%6,%7}, {%8,%9}, {%0,%1,%2,%3};"                  \
        : "+f"((d)[0]), "+f"((d)[1]), "+f"((d)[2]), "+f"((d)[3])                  \
        : "r"(a0), "r"(a1), "r"(a2), "r"(a3), "r"(b0), "r"(b1))

#define CP16(dst, src) \
    asm volatile("cp.async.cg.shared.global [%0], [%1], 16;" :: "r"(dst), "l"(src) : "memory")
#define CP_COMMIT()   asm volatile("cp.async.commit_group;" ::: "memory")
#define CP_WAIT(nn)   asm volatile("cp.async.wait_group %0;" :: "n"(nn) : "memory")

// ================= K1: Wh = h @ W  + B-fragment (bf16 hi/lo) =================
__global__ __launch_bounds__(256) void wh_kernel(const float* __restrict__ h,
                                                 const float* __restrict__ W) {
    __shared__ float Ws[64 * 64];
    const int t = threadIdx.x;
    const int col = t & 63;             // n
    const int rowgrp = t >> 6;
    const int i0 = blockIdx.x * 16;     // 16 consecutive k (= one kbg)

    float acc[4] = {0.f, 0.f, 0.f, 0.f};
    for (int kc = 0; kc < 4; kc++) {
        __syncthreads();
        float4* wsv = reinterpret_cast<float4*>(Ws);
        const float4* wgv = reinterpret_cast<const float4*>(W + kc * 64 * 64);
        #pragma unroll
        for (int q = 0; q < 4; q++) wsv[t + 256 * q] = wgv[t + 256 * q];
        __syncthreads();

        #pragma unroll 4
        for (int kk = 0; kk < 64; kk += 4) {
            const int k = kc * 64 + kk;
            const float w0 = Ws[(kk + 0) * 64 + col];
            const float w1 = Ws[(kk + 1) * 64 + col];
            const float w2 = Ws[(kk + 2) * 64 + col];
            const float w3 = Ws[(kk + 3) * 64 + col];
            #pragma unroll
            for (int rr = 0; rr < 4; rr++) {
                const int rrow = i0 + rowgrp * 4 + rr;
                const float4 hv = *reinterpret_cast<const float4*>(h + (size_t)rrow * INCH + k);
                acc[rr] += hv.x * w0 + hv.y * w1 + hv.z * w2 + hv.w * w3;
            }
        }
    }
    #pragma unroll
    for (int rr = 0; rr < 4; rr++)
        g_Wh[(size_t)(i0 + rowgrp * 4 + rr) * OUTCH + col] = acc[rr];

    // write into mma B-fragment layout (k = row index, n = col)
    const int kbg = i0 >> 4;
    const int nt = col >> 3;
    const int g = col & 7;
    uint32_t* bf = reinterpret_cast<uint32_t*>(g_Bfrag);
    #pragma unroll
    for (int p = 0; p < 2; p++) {
        const int kp = rowgrp * 4 + 2 * p;              // even k-in-16 offset
        const int slotbase = (kp < 8) ? 0 : 1;          // b0 or b1
        const int tq = (kp < 8) ? (kp >> 1) : ((kp - 8) >> 1);
        const int lane = g * 4 + tq;
        const float vlo = acc[2 * p], vhi = acc[2 * p + 1];
        const uint32_t hiw = bf16x2_pack(vlo, vhi);
        const float rlo = vlo - __uint_as_float(hiw << 16);
        const float rhi = vhi - __uint_as_float(hiw & 0xffff0000u);
        const uint32_t low = bf16x2_pack(rlo, rhi);
        const size_t base = ((size_t)(kbg * 8 + nt) * 32 + lane) * 4;
        bf[base + slotbase] = hiw;
        bf[base + slotbase + 2] = low;
    }
}

// ================= K2: s1/s2 + encoded global max =================
__global__ __launch_bounds__(256) void s_kernel(const float* __restrict__ a) {
    __shared__ float sm1[8], sm2[8];
    const int wid = threadIdx.x >> 5;
    const int lane = threadIdx.x & 31;
    const int i = blockIdx.x * 8 + wid;
    const float v1 = g_Wh[(size_t)i * 64 + lane];
    const float v2 = g_Wh[(size_t)i * 64 + 32 + lane];
    float p1 = v1 * a[lane] + v2 * a[32 + lane];
    float p2 = v1 * a[64 + lane] + v2 * a[96 + lane];
    #pragma unroll
    for (int o = 16; o; o >>= 1) {
        p1 += __shfl_xor_sync(0xffffffffu, p1, o);
        p2 += __shfl_xor_sync(0xffffffffu, p2, o);
    }
    if (lane == 0) { g_s1[i] = p1; g_s2[i] = p2; sm1[wid] = p1; sm2[wid] = p2; }
    __syncthreads();
    if (threadIdx.x == 0) {
        float m1 = sm1[0], m2 = sm2[0];
        #pragma unroll
        for (int q = 1; q < 8; q++) { m1 = fmaxf(m1, sm1[q]); m2 = fmaxf(m2, sm2[q]); }
        atomicMax(&g_m1u, fenc(m1));
        atomicMax(&g_m2u, fenc(m2));
    }
}

// ================= K3: per-node exp factors =================
__global__ __launch_bounds__(256) void epack_kernel() {
    const int i = blockIdx.x * 256 + threadIdx.x;
    if (i >= N) return;
    const float M1 = fdec(g_m1u), M2 = fdec(g_m2u);
    const float X = M1 + M2;
    const float L0 = (X >= 0.f) ? X : 0.5f * X;
    const float s1 = g_s1[i], s2 = g_s2[i];
    g_ar2[i] = make_float2(expf(s1 - M1), expf(0.5f * (s1 - M1)));
    g_ep2[i] = make_float2(expf(s2 - (L0 - M1)), expf(0.5f * s2 - L0 + 0.5f * M1));
}

// ================= K4: fused weights + mma.sync, cp.async-pipelined adj =================
__global__ __launch_bounds__(256, 1) void gat_mma(const int* __restrict__ adj) {
    extern __shared__ char sm[];
    const uint32_t sb = smem_u32(sm);

    const int t = threadIdx.x;
    const int w = t >> 5, lane = t & 31;
    const int g = lane >> 2, tq = lane & 3;
    const int split = blockIdx.x;
    const int rowbase = blockIdx.y * TIROWS;
    const int jbase = split * JSPAN;
    const int kbg0 = jbase >> 4;

    // cp.async source/dst precompute: 4 chunks of 16B per thread per stage
    const int crow = t >> 3;            // base row (q adds 32)
    const int cir = t & 7;              // 16B chunk within 128B row segment
    const int* asrc0 = adj + (size_t)(rowbase + crow) * N + jbase + cir * 4;
    const uint32_t adst0 = sb + crow * ADJ_PITCH + cir * 16;

    const int r1 = rowbase + w * 16 + g;
    const int r2 = r1 + 8;
    const float2 ar1 = g_ar2[r1];
    const float2 ar2v = g_ar2[r2];

    float acc[8][4];
    #pragma unroll
    for (int nt = 0; nt < 8; nt++)
        #pragma unroll
        for (int c = 0; c < 4; c++) acc[nt][c] = 0.f;
    float Z1 = 0.f, Z2 = 0.f;

    // prologue: issue STAGES-1 stages
    #pragma unroll
    for (int s = 0; s < STAGES - 1; s++) {
        const uint32_t stg = adst0 + s * STAGE_SZ;
        #pragma unroll
        for (int q = 0; q < 4; q++)
            CP16(stg + q * 32 * ADJ_PITCH, asrc0 + (size_t)q * 32 * N + s * 32);
        if (t < 16)
            CP16(sb + s * STAGE_SZ + ADJ_BYTES + t * 16, &g_ep2[jbase + s * 32 + t * 2]);
        CP_COMMIT();
    }

    const uint32_t myadj1 = sb + (w * 16 + g) * ADJ_PITCH;       // + stage + jloc*4
    const uint32_t myadj2 = myadj1 + 8 * ADJ_PITCH;

    for (int h = 0; h < NH; h++) {
        const int slot = h % STAGES;
        const uint32_t stg = sb + slot * STAGE_SZ;

        CP_WAIT(STAGES - 2);
        __syncthreads();

        // issue stage h+STAGES-1 into slot (h-1)%STAGES (safe: barrier above)
        if (h + STAGES - 1 < NH) {
            const int hs = h + STAGES - 1;
            const uint32_t ndst = adst0 + (hs % STAGES) * STAGE_SZ;
            #pragma unroll
            for (int q = 0; q < 4; q++)
                CP16(ndst + q * 32 * ADJ_PITCH, asrc0 + (size_t)q * 32 * N + hs * 32);
            if (t < 16)
                CP16(sb + (hs % STAGES) * STAGE_SZ + ADJ_BYTES + t * 16,
                     &g_ep2[jbase + hs * 32 + t * 2]);
            CP_COMMIT();
        }

        // ---- compute on stage h ----
        const char* eps = sm + slot * STAGE_SZ + ADJ_BYTES;
        #pragma unroll
        for (int kb = 0; kb < 2; kb++) {
            uint32_t ahi[4], alo[4];
            #pragma unroll
            for (int pr = 0; pr < 2; pr++) {
                const int jloc = kb * 16 + 2 * tq + pr * 8;
                const float4 e = *reinterpret_cast<const float4*>(eps + jloc * 8);
                const int2 m1 = *reinterpret_cast<const int2*>(sm + (myadj1 - sb) + slot * STAGE_SZ + jloc * 4);
                const int2 m2 = *reinterpret_cast<const int2*>(sm + (myadj2 - sb) + slot * STAGE_SZ + jloc * 4);
                const float w1a = m1.x ? fmaxf(ar1.x * e.x, ar1.y * e.y) : 0.f;
                const float w1b = m1.y ? fmaxf(ar1.x * e.z, ar1.y * e.w) : 0.f;
                const float w2a = m2.x ? fmaxf(ar2v.x * e.x, ar2v.y * e.y) : 0.f;
                const float w2b = m2.y ? fmaxf(ar2v.x * e.z, ar2v.y * e.w) : 0.f;
                Z1 += w1a + w1b;
                Z2 += w2a + w2b;
                const uint32_t h1 = bf16x2_pack(w1a, w1b);
                const uint32_t h2 = bf16x2_pack(w2a, w2b);
                ahi[2 * pr + 0] = h1;
                ahi[2 * pr + 1] = h2;
                alo[2 * pr + 0] = bf16x2_pack(w1a - __uint_as_float(h1 << 16),
                                              w1b - __uint_as_float(h1 & 0xffff0000u));
                alo[2 * pr + 1] = bf16x2_pack(w2a - __uint_as_float(h2 << 16),
                                              w2b - __uint_as_float(h2 & 0xffff0000u));
            }
            const int kbg = kbg0 + h * 2 + kb;
            const uint4* bp = g_Bfrag + ((size_t)kbg * 8) * 32 + lane;
            #pragma unroll
            for (int nt = 0; nt < 8; nt++) {
                const uint4 b = bp[nt * 32];
                MMA16816(acc[nt], ahi[0], ahi[1], ahi[2], ahi[3], b.x, b.y);
                MMA16816(acc[nt], ahi[0], ahi[1], ahi[2], ahi[3], b.z, b.w);
                MMA16816(acc[nt], alo[0], alo[1], alo[2], alo[3], b.x, b.y);
            }
        }
    }

    // Z reduce across the t-quad
    Z1 += __shfl_xor_sync(0xffffffffu, Z1, 1);
    Z1 += __shfl_xor_sync(0xffffffffu, Z1, 2);
    Z2 += __shfl_xor_sync(0xffffffffu, Z2, 1);
    Z2 += __shfl_xor_sync(0xffffffffu, Z2, 2);
    if (tq == 0) {
        g_Zp[split * N + r1] = Z1;
        g_Zp[split * N + r2] = Z2;
    }

    // store partial tile
    float* p1 = g_part + ((size_t)split * N + r1) * 64;
    float* p2 = g_part + ((size_t)split * N + r2) * 64;
    #pragma unroll
    for (int nt = 0; nt < 8; nt++) {
        const int c = nt * 8 + 2 * tq;
        *reinterpret_cast<float2*>(p1 + c) = make_float2(acc[nt][0], acc[nt][1]);
        *reinterpret_cast<float2*>(p2 + c) = make_float2(acc[nt][2], acc[nt][3]);
    }
}

// ================= K5: combine splits, normalize, relu =================
__global__ __launch_bounds__(256) void final_kernel(float* __restrict__ out) {
    const int idx = blockIdx.x * 256 + threadIdx.x;   // 8192*16 float4s
    const int row = idx >> 4;
    const int c4 = idx & 15;
    const float z = g_Zp[row] + g_Zp[N + row];
    const float inv = 1.f / z;
    const size_t off = (size_t)row * 64 + c4 * 4;
    float4 s = *reinterpret_cast<const float4*>(g_part + off);
    const float4 p = *reinterpret_cast<const float4*>(g_part + (size_t)N * 64 + off);
    s.x += p.x; s.y += p.y; s.z += p.z; s.w += p.w;
    *reinterpret_cast<float4*>(out + off) = make_float4(
        fmaxf(s.x * inv, 0.f), fmaxf(s.y * inv, 0.f),
        fmaxf(s.z * inv, 0.f), fmaxf(s.w * inv, 0.f));
}

// ================= launch =================
extern "C" void kernel_launch(void* const* d_in, const int* in_sizes, int n_in,
                              void* d_out, int out_size) {
    const float* h   = (const float*)d_in[0];
    const int*   adj = (const int*)d_in[1];
    const float* W   = (const float*)d_in[2];
    const float* a   = (const float*)d_in[3];
    float*       out = (float*)d_out;

    cudaFuncSetAttribute(gat_mma, cudaFuncAttributeMaxDynamicSharedMemorySize, SMEM_MAIN);

    wh_kernel<<<N / 16, 256>>>(h, W);
    s_kernel<<<N / 8, 256>>>(a);
    epack_kernel<<<N / 256, 256>>>();
    gat_mma<<<dim3(NSPLIT, N / TIROWS), 256, SMEM_MAIN>>>(adj);
    final_kernel<<<(N * 16) / 256, 256>>>(out);
}

// round 7
// speedup vs baseline: 1.5914x; 1.5914x over previous
#include <cuda_runtime.h>
#include <cuda_bf16.h>
#include <math.h>
#include <stdint.h>

#define N      8192
#define INCH   256
#define OUTCH  64
#define NSPLIT 4
#define JSPAN  (N / NSPLIT)     // 2048
#define TIROWS 128
#define NH     (JSPAN / 32)     // 64 halves (32 j each)

// ---------------- device scratch ----------------
__device__ float    g_Wh[N * OUTCH];
__device__ float    g_s1[N], g_s2[N];
__device__ unsigned g_m1u, g_m2u;                 // encoded float max (idempotent)
__device__ __align__(16) float2 g_ep2[N];         // (E1_j, Eh_j)
__device__ float2   g_ar2[N];                     // (A1_i, Ah_i)
__device__ unsigned g_adjT[(N / 32) * N];         // bit-packed adj [word][row]
// B in mma-fragment layout: [kbg 0..511][nt 0..7][lane 0..31] x uint4(b0hi,b1hi,b0lo,b1lo)
__device__ uint4    g_Bfrag[(N / 16) * 8 * 32];
__device__ float    g_part[NSPLIT * N * OUTCH];
__device__ float    g_Zp[NSPLIT * N];

__device__ __forceinline__ unsigned fenc(float f) {
    unsigned u = __float_as_uint(f);
    return (u & 0x80000000u) ? ~u : (u | 0x80000000u);
}
__device__ __forceinline__ float fdec(unsigned k) {
    return __uint_as_float((k & 0x80000000u) ? (k ^ 0x80000000u) : ~k);
}
__device__ __forceinline__ uint32_t bf16x2_pack(float lo, float hi) {
    uint32_t r;
    asm("cvt.rn.bf16x2.f32 %0, %1, %2;" : "=r"(r) : "f"(hi), "f"(lo));  // upper=hi, lower=lo
    return r;
}

#define MMA16816(d, a0, a1, a2, a3, b0, b1)                                       \
    asm volatile("mma.sync.aligned.m16n8k16.row.col.f32.bf16.bf16.f32 "          \
        "{%0,%1,%2,%3}, {%4,%5,%6,%7}, {%8,%9}, {%0,%1,%2,%3};"                  \
        : "+f"((d)[0]), "+f"((d)[1]), "+f"((d)[2]), "+f"((d)[3])                  \
        : "r"(a0), "r"(a1), "r"(a2), "r"(a3), "r"(b0), "r"(b1))

// ================= K0: bit-pack adjacency [word][row] =================
__global__ __launch_bounds__(1024) void bitpack_kernel(const int* __restrict__ adj) {
    __shared__ unsigned sw[32][33];
    const int wi = threadIdx.x >> 5, lane = threadIdx.x & 31;
    const int r0 = blockIdx.y * 32, w0 = blockIdx.x * 32;
    const int r = r0 + wi;
    const int* rowp = adj + (size_t)r * N + (size_t)w0 * 32;
    #pragma unroll
    for (int ww = 0; ww < 32; ww++) {
        const int v = rowp[ww * 32 + lane];
        const unsigned word = __ballot_sync(0xffffffffu, v != 0);
        if (lane == 0) sw[ww][wi] = word;
    }
    __syncthreads();
    g_adjT[(size_t)(w0 + wi) * N + r0 + lane] = sw[wi][lane];
}

// ================= K1: Wh = h @ W  + B-fragment (bf16 hi/lo) =================
__global__ __launch_bounds__(256) void wh_kernel(const float* __restrict__ h,
                                                 const float* __restrict__ W) {
    __shared__ float Ws[64 * 64];
    const int t = threadIdx.x;
    const int col = t & 63;             // n
    const int rowgrp = t >> 6;
    const int i0 = blockIdx.x * 16;     // 16 consecutive k (= one kbg)

    float acc[4] = {0.f, 0.f, 0.f, 0.f};
    for (int kc = 0; kc < 4; kc++) {
        __syncthreads();
        float4* wsv = reinterpret_cast<float4*>(Ws);
        const float4* wgv = reinterpret_cast<const float4*>(W + kc * 64 * 64);
        #pragma unroll
        for (int q = 0; q < 4; q++) wsv[t + 256 * q] = wgv[t + 256 * q];
        __syncthreads();

        #pragma unroll 4
        for (int kk = 0; kk < 64; kk += 4) {
            const int k = kc * 64 + kk;
            const float w0 = Ws[(kk + 0) * 64 + col];
            const float w1 = Ws[(kk + 1) * 64 + col];
            const float w2 = Ws[(kk + 2) * 64 + col];
            const float w3 = Ws[(kk + 3) * 64 + col];
            #pragma unroll
            for (int rr = 0; rr < 4; rr++) {
                const int rrow = i0 + rowgrp * 4 + rr;
                const float4 hv = *reinterpret_cast<const float4*>(h + (size_t)rrow * INCH + k);
                acc[rr] += hv.x * w0 + hv.y * w1 + hv.z * w2 + hv.w * w3;
            }
        }
    }
    #pragma unroll
    for (int rr = 0; rr < 4; rr++)
        g_Wh[(size_t)(i0 + rowgrp * 4 + rr) * OUTCH + col] = acc[rr];

    // write into mma B-fragment layout (k = row index, n = col)
    const int kbg = i0 >> 4;
    const int nt = col >> 3;
    const int g = col & 7;
    uint32_t* bf = reinterpret_cast<uint32_t*>(g_Bfrag);
    #pragma unroll
    for (int p = 0; p < 2; p++) {
        const int kp = rowgrp * 4 + 2 * p;              // even k-in-16 offset
        const int slotbase = (kp < 8) ? 0 : 1;          // b0 or b1
        const int tq = (kp < 8) ? (kp >> 1) : ((kp - 8) >> 1);
        const int lane = g * 4 + tq;
        const float vlo = acc[2 * p], vhi = acc[2 * p + 1];
        const uint32_t hiw = bf16x2_pack(vlo, vhi);
        const float rlo = vlo - __uint_as_float(hiw << 16);
        const float rhi = vhi - __uint_as_float(hiw & 0xffff0000u);
        const uint32_t low = bf16x2_pack(rlo, rhi);
        const size_t base = ((size_t)(kbg * 8 + nt) * 32 + lane) * 4;
        bf[base + slotbase] = hiw;
        bf[base + slotbase + 2] = low;
    }
}

// ================= K2: s1/s2 + encoded global max =================
__global__ __launch_bounds__(256) void s_kernel(const float* __restrict__ a) {
    __shared__ float sm1[8], sm2[8];
    const int wid = threadIdx.x >> 5;
    const int lane = threadIdx.x & 31;
    const int i = blockIdx.x * 8 + wid;
    const float v1 = g_Wh[(size_t)i * 64 + lane];
    const float v2 = g_Wh[(size_t)i * 64 + 32 + lane];
    float p1 = v1 * a[lane] + v2 * a[32 + lane];
    float p2 = v1 * a[64 + lane] + v2 * a[96 + lane];
    #pragma unroll
    for (int o = 16; o; o >>= 1) {
        p1 += __shfl_xor_sync(0xffffffffu, p1, o);
        p2 += __shfl_xor_sync(0xffffffffu, p2, o);
    }
    if (lane == 0) { g_s1[i] = p1; g_s2[i] = p2; sm1[wid] = p1; sm2[wid] = p2; }
    __syncthreads();
    if (threadIdx.x == 0) {
        float m1 = sm1[0], m2 = sm2[0];
        #pragma unroll
        for (int q = 1; q < 8; q++) { m1 = fmaxf(m1, sm1[q]); m2 = fmaxf(m2, sm2[q]); }
        atomicMax(&g_m1u, fenc(m1));
        atomicMax(&g_m2u, fenc(m2));
    }
}

// ================= K3: per-node exp factors =================
__global__ __launch_bounds__(256) void epack_kernel() {
    const int i = blockIdx.x * 256 + threadIdx.x;
    if (i >= N) return;
    const float M1 = fdec(g_m1u), M2 = fdec(g_m2u);
    const float X = M1 + M2;
    const float L0 = (X >= 0.f) ? X : 0.5f * X;
    const float s1 = g_s1[i], s2 = g_s2[i];
    g_ar2[i] = make_float2(expf(s1 - M1), expf(0.5f * (s1 - M1)));
    g_ep2[i] = make_float2(expf(s2 - (L0 - M1)), expf(0.5f * s2 - L0 + 0.5f * M1));
}

// ================= K4: fused weights + mma.sync (packed adj, 2 CTA/SM) =================
#define LOAD_HALF(AW1, AW2, EP, HH) do {                                          \
    const int _j0 = jbase + (HH) * 32;                                            \
    AW1 = g_adjT[(size_t)(wb0 + (HH)) * N + r1];                                  \
    AW2 = g_adjT[(size_t)(wb0 + (HH)) * N + r2];                                  \
    _Pragma("unroll")                                                             \
    for (int _kb = 0; _kb < 2; _kb++)                                             \
        _Pragma("unroll")                                                         \
        for (int _pr = 0; _pr < 2; _pr++)                                         \
            EP[_kb][_pr] = *reinterpret_cast<const float4*>(                      \
                &g_ep2[_j0 + _kb * 16 + 2 * tq + _pr * 8]);                       \
} while (0)

__global__ __launch_bounds__(256, 2) void gat_mma() {
    const int t = threadIdx.x;
    const int w = t >> 5, lane = t & 31;
    const int g = lane >> 2, tq = lane & 3;
    const int split = blockIdx.x;
    const int rowbase = blockIdx.y * TIROWS;
    const int jbase = split * JSPAN;
    const int kbg0 = jbase >> 4;
    const int wb0 = jbase >> 5;

    const int r1 = rowbase + w * 16 + g;
    const int r2 = r1 + 8;
    const float2 ar1 = g_ar2[r1];
    const float2 ar2v = g_ar2[r2];

    float acc[8][4];
    #pragma unroll
    for (int nt = 0; nt < 8; nt++)
        #pragma unroll
        for (int c = 0; c < 4; c++) acc[nt][c] = 0.f;
    float Z1 = 0.f, Z2 = 0.f;

    unsigned aw1_0, aw2_0, aw1_1, aw2_1;
    float4 ep0[2][2], ep1[2][2];
    LOAD_HALF(aw1_0, aw2_0, ep0, 0);
    LOAD_HALF(aw1_1, aw2_1, ep1, 1);

    for (int hh = 0; hh < NH; hh += 2) {
        #pragma unroll
        for (int sub = 0; sub < 2; sub++) {
            const int h = hh + sub;
            const unsigned aw1 = sub ? aw1_1 : aw1_0;
            const unsigned aw2 = sub ? aw2_1 : aw2_0;
            #pragma unroll
            for (int kb = 0; kb < 2; kb++) {
                uint32_t ahi[4], alo[4];
                #pragma unroll
                for (int pr = 0; pr < 2; pr++) {
                    const float4 e = sub ? ep1[kb][pr] : ep0[kb][pr];
                    const int jloc = kb * 16 + 2 * tq + pr * 8;
                    const float w1a = ((aw1 >> jloc) & 1u) ? fmaxf(ar1.x * e.x, ar1.y * e.y) : 0.f;
                    const float w1b = ((aw1 >> (jloc + 1)) & 1u) ? fmaxf(ar1.x * e.z, ar1.y * e.w) : 0.f;
                    const float w2a = ((aw2 >> jloc) & 1u) ? fmaxf(ar2v.x * e.x, ar2v.y * e.y) : 0.f;
                    const float w2b = ((aw2 >> (jloc + 1)) & 1u) ? fmaxf(ar2v.x * e.z, ar2v.y * e.w) : 0.f;
                    Z1 += w1a + w1b;
                    Z2 += w2a + w2b;
                    const uint32_t h1 = bf16x2_pack(w1a, w1b);
                    const uint32_t h2 = bf16x2_pack(w2a, w2b);
                    ahi[2 * pr + 0] = h1;
                    ahi[2 * pr + 1] = h2;
                    alo[2 * pr + 0] = bf16x2_pack(w1a - __uint_as_float(h1 << 16),
                                                  w1b - __uint_as_float(h1 & 0xffff0000u));
                    alo[2 * pr + 1] = bf16x2_pack(w2a - __uint_as_float(h2 << 16),
                                                  w2b - __uint_as_float(h2 & 0xffff0000u));
                }
                const int kbg = kbg0 + h * 2 + kb;
                const uint4* bp = g_Bfrag + ((size_t)kbg * 8) * 32 + lane;
                #pragma unroll
                for (int nt = 0; nt < 8; nt++) {
                    const uint4 b = bp[nt * 32];
                    MMA16816(acc[nt], ahi[0], ahi[1], ahi[2], ahi[3], b.x, b.y);
                    MMA16816(acc[nt], ahi[0], ahi[1], ahi[2], ahi[3], b.z, b.w);
                    MMA16816(acc[nt], alo[0], alo[1], alo[2], alo[3], b.x, b.y);
                }
            }
            // refill the buffer just consumed (prefetch 2 halves ahead)
            if (sub == 0) { if (hh + 2 < NH) LOAD_HALF(aw1_0, aw2_0, ep0, hh + 2); }
            else          { if (hh + 3 < NH) LOAD_HALF(aw1_1, aw2_1, ep1, hh + 3); }
        }
    }

    // Z reduce across the t-quad
    Z1 += __shfl_xor_sync(0xffffffffu, Z1, 1);
    Z1 += __shfl_xor_sync(0xffffffffu, Z1, 2);
    Z2 += __shfl_xor_sync(0xffffffffu, Z2, 1);
    Z2 += __shfl_xor_sync(0xffffffffu, Z2, 2);
    if (tq == 0) {
        g_Zp[split * N + r1] = Z1;
        g_Zp[split * N + r2] = Z2;
    }

    // store partial tile
    float* p1 = g_part + ((size_t)split * N + r1) * 64;
    float* p2 = g_part + ((size_t)split * N + r2) * 64;
    #pragma unroll
    for (int nt = 0; nt < 8; nt++) {
        const int c = nt * 8 + 2 * tq;
        *reinterpret_cast<float2*>(p1 + c) = make_float2(acc[nt][0], acc[nt][1]);
        *reinterpret_cast<float2*>(p2 + c) = make_float2(acc[nt][2], acc[nt][3]);
    }
}

// ================= K5: combine splits, normalize, relu =================
__global__ __launch_bounds__(256) void final_kernel(float* __restrict__ out) {
    const int idx = blockIdx.x * 256 + threadIdx.x;   // 8192*16 float4s
    const int row = idx >> 4;
    const int c4 = idx & 15;
    const float z = g_Zp[row] + g_Zp[N + row] + g_Zp[2 * N + row] + g_Zp[3 * N + row];
    const float inv = 1.f / z;
    const size_t off = (size_t)row * 64 + c4 * 4;
    float4 s = *reinterpret_cast<const float4*>(g_part + off);
    #pragma unroll
    for (int sp = 1; sp < NSPLIT; sp++) {
        const float4 p = *reinterpret_cast<const float4*>(g_part + (size_t)sp * N * 64 + off);
        s.x += p.x; s.y += p.y; s.z += p.z; s.w += p.w;
    }
    *reinterpret_cast<float4*>(out + off) = make_float4(
        fmaxf(s.x * inv, 0.f), fmaxf(s.y * inv, 0.f),
        fmaxf(s.z * inv, 0.f), fmaxf(s.w * inv, 0.f));
}

// ================= launch =================
extern "C" void kernel_launch(void* const* d_in, const int* in_sizes, int n_in,
                              void* d_out, int out_size) {
    const float* h   = (const float*)d_in[0];
    const int*   adj = (const int*)d_in[1];
    const float* W   = (const float*)d_in[2];
    const float* a   = (const float*)d_in[3];
    float*       out = (float*)d_out;

    bitpack_kernel<<<dim3(N / 1024, N / 32), 1024>>>(adj);
    wh_kernel<<<N / 16, 256>>>(h, W);
    s_kernel<<<N / 8, 256>>>(a);
    epack_kernel<<<N / 256, 256>>>();
    gat_mma<<<dim3(NSPLIT, N / TIROWS), 256>>>();
    final_kernel<<<(N * 16) / 256, 256>>>(out);
}

// round 8
// speedup vs baseline: 1.6925x; 1.0635x over previous
#include <cuda_runtime.h>
#include <cuda_fp16.h>
#include <math.h>
#include <stdint.h>

#define N      8192
#define INCH   256
#define OUTCH  64
#define NSPLIT 4
#define JSPAN  (N / NSPLIT)     // 2048
#define TIROWS 128
#define NH     (JSPAN / 32)     // 64 halves (32 j each)

// ---------------- device scratch ----------------
__device__ float    g_Wh[N * OUTCH];
__device__ float    g_s1[N], g_s2[N];
__device__ unsigned g_m1u, g_m2u;                 // encoded float max (idempotent)
__device__ __align__(16) float2 g_ep2[N];         // (E1_j, Eh_j)
__device__ float2   g_ar2[N];                     // (A1_i, Ah_i)
__device__ unsigned g_adjT[(N / 32) * N];         // bit-packed adj [word][row]
// B in mma-fragment layout: [kbg 0..511][nt 0..7][lane 0..31] x uint4(b0hi,b1hi,b0lo,b1lo) fp16x2
__device__ uint4    g_Bfrag[(N / 16) * 8 * 32];
__device__ float    g_part[NSPLIT * N * OUTCH];
__device__ float    g_Zp[NSPLIT * N];

__device__ __forceinline__ unsigned fenc(float f) {
    unsigned u = __float_as_uint(f);
    return (u & 0x80000000u) ? ~u : (u | 0x80000000u);
}
__device__ __forceinline__ float fdec(unsigned k) {
    return __uint_as_float((k & 0x80000000u) ? (k ^ 0x80000000u) : ~k);
}
// pack two f32 -> f16x2 with lo in lower half, hi in upper half
__device__ __forceinline__ uint32_t f16x2_pack(float lo, float hi) {
    uint32_t r;
    asm("cvt.rn.f16x2.f32 %0, %1, %2;" : "=r"(r) : "f"(hi), "f"(lo));
    return r;
}

#define MMA16816(d, a0, a1, a2, a3, b0, b1)                                       \
    asm volatile("mma.sync.aligned.m16n8k16.row.col.f32.f16.f16.f32 "            \
        "{%0,%1,%2,%3}, {%4,%5,%6,%7}, {%8,%9}, {%0,%1,%2,%3};"                  \
        : "+f"((d)[0]), "+f"((d)[1]), "+f"((d)[2]), "+f"((d)[3])                  \
        : "r"(a0), "r"(a1), "r"(a2), "r"(a3), "r"(b0), "r"(b1))

// ================= K0: bit-pack adjacency [word][row] =================
__global__ __launch_bounds__(1024) void bitpack_kernel(const int* __restrict__ adj) {
    __shared__ unsigned sw[32][33];
    const int wi = threadIdx.x >> 5, lane = threadIdx.x & 31;
    const int r0 = blockIdx.y * 32, w0 = blockIdx.x * 32;
    const int r = r0 + wi;
    const int* rowp = adj + (size_t)r * N + (size_t)w0 * 32;
    #pragma unroll
    for (int ww = 0; ww < 32; ww++) {
        const int v = rowp[ww * 32 + lane];
        const unsigned word = __ballot_sync(0xffffffffu, v != 0);
        if (lane == 0) sw[ww][wi] = word;
    }
    __syncthreads();
    g_adjT[(size_t)(w0 + wi) * N + r0 + lane] = sw[wi][lane];
}

// ================= K1: Wh = h @ W  + B-fragment (fp16 hi/lo) =================
__global__ __launch_bounds__(256) void wh_kernel(const float* __restrict__ h,
                                                 const float* __restrict__ W) {
    __shared__ float Ws[64 * 64];
    const int t = threadIdx.x;
    const int col = t & 63;             // n
    const int rowgrp = t >> 6;
    const int i0 = blockIdx.x * 16;     // 16 consecutive k (= one kbg)

    float acc[4] = {0.f, 0.f, 0.f, 0.f};
    for (int kc = 0; kc < 4; kc++) {
        __syncthreads();
        float4* wsv = reinterpret_cast<float4*>(Ws);
        const float4* wgv = reinterpret_cast<const float4*>(W + kc * 64 * 64);
        #pragma unroll
        for (int q = 0; q < 4; q++) wsv[t + 256 * q] = wgv[t + 256 * q];
        __syncthreads();

        #pragma unroll 4
        for (int kk = 0; kk < 64; kk += 4) {
            const int k = kc * 64 + kk;
            const float w0 = Ws[(kk + 0) * 64 + col];
            const float w1 = Ws[(kk + 1) * 64 + col];
            const float w2 = Ws[(kk + 2) * 64 + col];
            const float w3 = Ws[(kk + 3) * 64 + col];
            #pragma unroll
            for (int rr = 0; rr < 4; rr++) {
                const int rrow = i0 + rowgrp * 4 + rr;
                const float4 hv = *reinterpret_cast<const float4*>(h + (size_t)rrow * INCH + k);
                acc[rr] += hv.x * w0 + hv.y * w1 + hv.z * w2 + hv.w * w3;
            }
        }
    }
    #pragma unroll
    for (int rr = 0; rr < 4; rr++)
        g_Wh[(size_t)(i0 + rowgrp * 4 + rr) * OUTCH + col] = acc[rr];

    // write into mma B-fragment layout (k = row index, n = col), fp16 hi/lo
    const int kbg = i0 >> 4;
    const int nt = col >> 3;
    const int g = col & 7;
    uint32_t* bf = reinterpret_cast<uint32_t*>(g_Bfrag);
    #pragma unroll
    for (int p = 0; p < 2; p++) {
        const int kp = rowgrp * 4 + 2 * p;              // even k-in-16 offset
        const int slotbase = (kp < 8) ? 0 : 1;          // b0 or b1
        const int tq = (kp < 8) ? (kp >> 1) : ((kp - 8) >> 1);
        const int lane = g * 4 + tq;
        const float vlo = acc[2 * p], vhi = acc[2 * p + 1];
        const __half hlo = __float2half_rn(vlo);
        const __half hhi = __float2half_rn(vhi);
        const __half2 hw = __halves2half2(hlo, hhi);    // lower=even k, upper=odd k
        const float rlo = vlo - __half2float(hlo);
        const float rhi = vhi - __half2float(hhi);
        const uint32_t low = f16x2_pack(rlo, rhi);
        const size_t base = ((size_t)(kbg * 8 + nt) * 32 + lane) * 4;
        bf[base + slotbase] = *reinterpret_cast<const uint32_t*>(&hw);
        bf[base + slotbase + 2] = low;
    }
}

// ================= K2: s1/s2 + encoded global max =================
__global__ __launch_bounds__(256) void s_kernel(const float* __restrict__ a) {
    __shared__ float sm1[8], sm2[8];
    const int wid = threadIdx.x >> 5;
    const int lane = threadIdx.x & 31;
    const int i = blockIdx.x * 8 + wid;
    const float v1 = g_Wh[(size_t)i * 64 + lane];
    const float v2 = g_Wh[(size_t)i * 64 + 32 + lane];
    float p1 = v1 * a[lane] + v2 * a[32 + lane];
    float p2 = v1 * a[64 + lane] + v2 * a[96 + lane];
    #pragma unroll
    for (int o = 16; o; o >>= 1) {
        p1 += __shfl_xor_sync(0xffffffffu, p1, o);
        p2 += __shfl_xor_sync(0xffffffffu, p2, o);
    }
    if (lane == 0) { g_s1[i] = p1; g_s2[i] = p2; sm1[wid] = p1; sm2[wid] = p2; }
    __syncthreads();
    if (threadIdx.x == 0) {
        float m1 = sm1[0], m2 = sm2[0];
        #pragma unroll
        for (int q = 1; q < 8; q++) { m1 = fmaxf(m1, sm1[q]); m2 = fmaxf(m2, sm2[q]); }
        atomicMax(&g_m1u, fenc(m1));
        atomicMax(&g_m2u, fenc(m2));
    }
}

// ================= K3: per-node exp factors =================
__global__ __launch_bounds__(256) void epack_kernel() {
    const int i = blockIdx.x * 256 + threadIdx.x;
    if (i >= N) return;
    const float M1 = fdec(g_m1u), M2 = fdec(g_m2u);
    const float X = M1 + M2;
    const float L0 = (X >= 0.f) ? X : 0.5f * X;
    const float s1 = g_s1[i], s2 = g_s2[i];
    g_ar2[i] = make_float2(expf(s1 - M1), expf(0.5f * (s1 - M1)));
    g_ep2[i] = make_float2(expf(s2 - (L0 - M1)), expf(0.5f * s2 - L0 + 0.5f * M1));
}

// ================= K4: fused weights + fp16 mma (packed adj, 2 CTA/SM) =================
#define LOAD_HALF(AW1, AW2, EP, HH) do {                                          \
    const int _j0 = jbase + (HH) * 32;                                            \
    AW1 = g_adjT[(size_t)(wb0 + (HH)) * N + r1];                                  \
    AW2 = g_adjT[(size_t)(wb0 + (HH)) * N + r2];                                  \
    _Pragma("unroll")                                                             \
    for (int _kb = 0; _kb < 2; _kb++)                                             \
        _Pragma("unroll")                                                         \
        for (int _pr = 0; _pr < 2; _pr++)                                         \
            EP[_kb][_pr] = *reinterpret_cast<const float4*>(                      \
                &g_ep2[_j0 + _kb * 16 + 2 * tq + _pr * 8]);                       \
} while (0)

__global__ __launch_bounds__(256, 2) void gat_mma() {
    const int t = threadIdx.x;
    const int w = t >> 5, lane = t & 31;
    const int g = lane >> 2, tq = lane & 3;
    const int split = blockIdx.x;
    const int rowbase = blockIdx.y * TIROWS;
    const int jbase = split * JSPAN;
    const int kbg0 = jbase >> 4;
    const int wb0 = jbase >> 5;

    const int r1 = rowbase + w * 16 + g;
    const int r2 = r1 + 8;
    const float2 ar1 = g_ar2[r1];
    const float2 ar2v = g_ar2[r2];

    float acc[8][4];
    #pragma unroll
    for (int nt = 0; nt < 8; nt++)
        #pragma unroll
        for (int c = 0; c < 4; c++) acc[nt][c] = 0.f;
    float Z1 = 0.f, Z2 = 0.f;

    unsigned aw1_0, aw2_0, aw1_1, aw2_1;
    float4 ep0[2][2], ep1[2][2];
    LOAD_HALF(aw1_0, aw2_0, ep0, 0);
    LOAD_HALF(aw1_1, aw2_1, ep1, 1);

    for (int hh = 0; hh < NH; hh += 2) {
        #pragma unroll
        for (int sub = 0; sub < 2; sub++) {
            const int h = hh + sub;
            const unsigned aw1 = sub ? aw1_1 : aw1_0;
            const unsigned aw2 = sub ? aw2_1 : aw2_0;
            const int kbg = kbg0 + h * 2;

            // preload kb0's B fragments (latency hidden under weight gen)
            uint4 bpre[8];
            {
                const uint4* bp = g_Bfrag + ((size_t)kbg * 8) * 32 + lane;
                #pragma unroll
                for (int nt = 0; nt < 8; nt++) bpre[nt] = bp[nt * 32];
            }

            #pragma unroll
            for (int kb = 0; kb < 2; kb++) {
                uint32_t ahi[4];
                #pragma unroll
                for (int pr = 0; pr < 2; pr++) {
                    const float4 e = sub ? ep1[kb][pr] : ep0[kb][pr];
                    const int jloc = kb * 16 + 2 * tq + pr * 8;
                    const float w1a = ((aw1 >> jloc) & 1u) ? fmaxf(ar1.x * e.x, ar1.y * e.y) : 0.f;
                    const float w1b = ((aw1 >> (jloc + 1)) & 1u) ? fmaxf(ar1.x * e.z, ar1.y * e.w) : 0.f;
                    const float w2a = ((aw2 >> jloc) & 1u) ? fmaxf(ar2v.x * e.x, ar2v.y * e.y) : 0.f;
                    const float w2b = ((aw2 >> (jloc + 1)) & 1u) ? fmaxf(ar2v.x * e.z, ar2v.y * e.w) : 0.f;
                    Z1 += w1a + w1b;
                    Z2 += w2a + w2b;
                    ahi[2 * pr + 0] = f16x2_pack(w1a, w1b);
                    ahi[2 * pr + 1] = f16x2_pack(w2a, w2b);
                }
                const uint4* bp1 = g_Bfrag + ((size_t)(kbg + 1) * 8) * 32 + lane;
                #pragma unroll
                for (int nt = 0; nt < 8; nt++) {
                    const uint4 b = kb ? bp1[nt * 32] : bpre[nt];
                    MMA16816(acc[nt], ahi[0], ahi[1], ahi[2], ahi[3], b.x, b.y);
                    MMA16816(acc[nt], ahi[0], ahi[1], ahi[2], ahi[3], b.z, b.w);
                }
            }
            // refill the buffer just consumed (prefetch 2 halves ahead)
            if (sub == 0) { if (hh + 2 < NH) LOAD_HALF(aw1_0, aw2_0, ep0, hh + 2); }
            else          { if (hh + 3 < NH) LOAD_HALF(aw1_1, aw2_1, ep1, hh + 3); }
        }
    }

    // Z reduce across the t-quad
    Z1 += __shfl_xor_sync(0xffffffffu, Z1, 1);
    Z1 += __shfl_xor_sync(0xffffffffu, Z1, 2);
    Z2 += __shfl_xor_sync(0xffffffffu, Z2, 1);
    Z2 += __shfl_xor_sync(0xffffffffu, Z2, 2);
    if (tq == 0) {
        g_Zp[split * N + r1] = Z1;
        g_Zp[split * N + r2] = Z2;
    }

    // store partial tile
    float* p1 = g_part + ((size_t)split * N + r1) * 64;
    float* p2 = g_part + ((size_t)split * N + r2) * 64;
    #pragma unroll
    for (int nt = 0; nt < 8; nt++) {
        const int c = nt * 8 + 2 * tq;
        *reinterpret_cast<float2*>(p1 + c) = make_float2(acc[nt][0], acc[nt][1]);
        *reinterpret_cast<float2*>(p2 + c) = make_float2(acc[nt][2], acc[nt][3]);
    }
}

// ================= K5: combine splits, normalize, relu =================
__global__ __launch_bounds__(256) void final_kernel(float* __restrict__ out) {
    const int idx = blockIdx.x * 256 + threadIdx.x;   // 8192*16 float4s
    const int row = idx >> 4;
    const int c4 = idx & 15;
    const float z = g_Zp[row] + g_Zp[N + row] + g_Zp[2 * N + row] + g_Zp[3 * N + row];
    const float inv = 1.f / z;
    const size_t off = (size_t)row * 64 + c4 * 4;
    float4 s = *reinterpret_cast<const float4*>(g_part + off);
    #pragma unroll
    for (int sp = 1; sp < NSPLIT; sp++) {
        const float4 p = *reinterpret_cast<const float4*>(g_part + (size_t)sp * N * 64 + off);
        s.x += p.x; s.y += p.y; s.z += p.z; s.w += p.w;
    }
    *reinterpret_cast<float4*>(out + off) = make_float4(
        fmaxf(s.x * inv, 0.f), fmaxf(s.y * inv, 0.f),
        fmaxf(s.z * inv, 0.f), fmaxf(s.w * inv, 0.f));
}

// ================= launch =================
extern "C" void kernel_launch(void* const* d_in, const int* in_sizes, int n_in,
                              void* d_out, int out_size) {
    const float* h   = (const float*)d_in[0];
    const int*   adj = (const int*)d_in[1];
    const float* W   = (const float*)d_in[2];
    const float* a   = (const float*)d_in[3];
    float*       out = (float*)d_out;

    bitpack_kernel<<<dim3(N / 1024, N / 32), 1024>>>(adj);
    wh_kernel<<<N / 16, 256>>>(h, W);
    s_kernel<<<N / 8, 256>>>(a);
    epack_kernel<<<N / 256, 256>>>();
    gat_mma<<<dim3(NSPLIT, N / TIROWS), 256>>>();
    final_kernel<<<(N * 16) / 256, 256>>>(out);
}

// round 9
// speedup vs baseline: 2.2568x; 1.3334x over previous
#include <cuda_runtime.h>
#include <cuda_fp16.h>
#include <math.h>
#include <stdint.h>

#define N      8192
#define INCH   256
#define OUTCH  64
#define NSPLIT 4
#define JSPAN  (N / NSPLIT)     // 2048
#define TIROWS 128
#define NH     (JSPAN / 32)     // 64 halves (32 j each)

// ---------------- device scratch ----------------
__device__ float    g_Wh[N * OUTCH];
__device__ float    g_s1[N], g_s2[N];
__device__ unsigned g_m1u, g_m2u;                 // encoded float max (idempotent)
__device__ __align__(16) float2 g_ep2[N];         // (E1_j, Eh_j)
__device__ float2   g_ar2[N];                     // (A1_i, Ah_i)
__device__ unsigned g_adjT[(N / 32) * N];         // bit-packed adj [word][row]
// B in mma-fragment layout: [kbg 0..511][nt 0..7][lane 0..31] x uint4(b0hi,b1hi,b0lo,b1lo) fp16x2
__device__ uint4    g_Bfrag[(N / 16) * 8 * 32];
__device__ float    g_part[NSPLIT * N * OUTCH];
__device__ float    g_Zp[NSPLIT * N];

__device__ __forceinline__ unsigned fenc(float f) {
    unsigned u = __float_as_uint(f);
    return (u & 0x80000000u) ? ~u : (u | 0x80000000u);
}
__device__ __forceinline__ float fdec(unsigned k) {
    return __uint_as_float((k & 0x80000000u) ? (k ^ 0x80000000u) : ~k);
}
// pack two f32 -> f16x2 with lo in lower half, hi in upper half
__device__ __forceinline__ uint32_t f16x2_pack(float lo, float hi) {
    uint32_t r;
    asm("cvt.rn.f16x2.f32 %0, %1, %2;" : "=r"(r) : "f"(hi), "f"(lo));
    return r;
}

#define MMA16816(d, a0, a1, a2, a3, b0, b1)                                       \
    asm volatile("mma.sync.aligned.m16n8k16.row.col.f32.f16.f16.f32 "            \
        "{%0,%1,%2,%3}, {%4,%5,%6,%7}, {%8,%9}, {%0,%1,%2,%3};"                  \
        : "+f"((d)[0]), "+f"((d)[1]), "+f"((d)[2]), "+f"((d)[3])                  \
        : "r"(a0), "r"(a1), "r"(a2), "r"(a3), "r"(b0), "r"(b1))

// ================= K0: fused wh-GEMM (blocks 0..511) + adj bitpack (rest) ======
// wh blocks are compute-bound, bitpack blocks are DRAM-bound; interleaving them
// in one launch overlaps the two.
#define WH_BLOCKS   (N / 16)          // 512
#define BP_BLOCKS   (8 * (N / 8))     // 8192 (8 word-groups x 1024 row-groups)

__global__ __launch_bounds__(256) void fused0_kernel(const float* __restrict__ h,
                                                     const float* __restrict__ W,
                                                     const int* __restrict__ adj) {
    __shared__ __align__(16) char smraw[64 * 64 * 4];
    const int t = threadIdx.x;
    const int bid = blockIdx.x;

    if (bid < WH_BLOCKS) {
        // ---------------- wh part ----------------
        float* Ws = reinterpret_cast<float*>(smraw);
        const int col = t & 63;             // n
        const int rowgrp = t >> 6;
        const int i0 = bid * 16;            // 16 consecutive k (= one kbg)

        float acc[4] = {0.f, 0.f, 0.f, 0.f};
        for (int kc = 0; kc < 4; kc++) {
            __syncthreads();
            float4* wsv = reinterpret_cast<float4*>(Ws);
            const float4* wgv = reinterpret_cast<const float4*>(W + kc * 64 * 64);
            #pragma unroll
            for (int q = 0; q < 4; q++) wsv[t + 256 * q] = wgv[t + 256 * q];
            __syncthreads();

            #pragma unroll 4
            for (int kk = 0; kk < 64; kk += 4) {
                const int k = kc * 64 + kk;
                const float w0 = Ws[(kk + 0) * 64 + col];
                const float w1 = Ws[(kk + 1) * 64 + col];
                const float w2 = Ws[(kk + 2) * 64 + col];
                const float w3 = Ws[(kk + 3) * 64 + col];
                #pragma unroll
                for (int rr = 0; rr < 4; rr++) {
                    const int rrow = i0 + rowgrp * 4 + rr;
                    const float4 hv = *reinterpret_cast<const float4*>(h + (size_t)rrow * INCH + k);
                    acc[rr] += hv.x * w0 + hv.y * w1 + hv.z * w2 + hv.w * w3;
                }
            }
        }
        #pragma unroll
        for (int rr = 0; rr < 4; rr++)
            g_Wh[(size_t)(i0 + rowgrp * 4 + rr) * OUTCH + col] = acc[rr];

        // B fragment (fp16 hi/lo), k = row index, n = col
        const int kbg = i0 >> 4;
        const int nt = col >> 3;
        const int g = col & 7;
        uint32_t* bf = reinterpret_cast<uint32_t*>(g_Bfrag);
        #pragma unroll
        for (int p = 0; p < 2; p++) {
            const int kp = rowgrp * 4 + 2 * p;
            const int slotbase = (kp < 8) ? 0 : 1;
            const int tq = (kp < 8) ? (kp >> 1) : ((kp - 8) >> 1);
            const int lane = g * 4 + tq;
            const float vlo = acc[2 * p], vhi = acc[2 * p + 1];
            const __half hlo = __float2half_rn(vlo);
            const __half hhi = __float2half_rn(vhi);
            const __half2 hw = __halves2half2(hlo, hhi);
            const float rlo = vlo - __half2float(hlo);
            const float rhi = vhi - __half2float(hhi);
            const uint32_t low = f16x2_pack(rlo, rhi);
            const size_t base = ((size_t)(kbg * 8 + nt) * 32 + lane) * 4;
            bf[base + slotbase] = *reinterpret_cast<const uint32_t*>(&hw);
            bf[base + slotbase + 2] = low;
        }
    } else {
        // ---------------- bitpack part: 8 rows x 1024 j per block ----------------
        unsigned* sw = reinterpret_cast<unsigned*>(smraw);   // [32 words][9]
        const int b = bid - WH_BLOCKS;
        const int bx = b & 7;              // word-group: words [bx*32, bx*32+32)
        const int ry = b >> 3;             // row-group: rows [ry*8, ry*8+8)
        const int wi = t >> 5, lane = t & 31;
        const int r = ry * 8 + wi;
        const int* rowp = adj + (size_t)r * N + (size_t)bx * 1024;
        #pragma unroll
        for (int ww = 0; ww < 32; ww++) {
            const int v = rowp[ww * 32 + lane];
            const unsigned word = __ballot_sync(0xffffffffu, v != 0);
            if (lane == 0) sw[ww * 9 + wi] = word;
        }
        __syncthreads();
        const int word = t >> 3, row = t & 7;
        g_adjT[(size_t)(bx * 32 + word) * N + ry * 8 + row] = sw[word * 9 + row];
    }
}

// ================= K2: s1/s2 + encoded global max =================
__global__ __launch_bounds__(256) void s_kernel(const float* __restrict__ a) {
    __shared__ float sm1[8], sm2[8];
    const int wid = threadIdx.x >> 5;
    const int lane = threadIdx.x & 31;
    const int i = blockIdx.x * 8 + wid;
    const float v1 = g_Wh[(size_t)i * 64 + lane];
    const float v2 = g_Wh[(size_t)i * 64 + 32 + lane];
    float p1 = v1 * a[lane] + v2 * a[32 + lane];
    float p2 = v1 * a[64 + lane] + v2 * a[96 + lane];
    #pragma unroll
    for (int o = 16; o; o >>= 1) {
        p1 += __shfl_xor_sync(0xffffffffu, p1, o);
        p2 += __shfl_xor_sync(0xffffffffu, p2, o);
    }
    if (lane == 0) { g_s1[i] = p1; g_s2[i] = p2; sm1[wid] = p1; sm2[wid] = p2; }
    __syncthreads();
    if (threadIdx.x == 0) {
        float m1 = sm1[0], m2 = sm2[0];
        #pragma unroll
        for (int q = 1; q < 8; q++) { m1 = fmaxf(m1, sm1[q]); m2 = fmaxf(m2, sm2[q]); }
        atomicMax(&g_m1u, fenc(m1));
        atomicMax(&g_m2u, fenc(m2));
    }
}

// ================= K3: per-node exp factors =================
__global__ __launch_bounds__(128) void epack_kernel() {
    const int i = blockIdx.x * 128 + threadIdx.x;
    if (i >= N) return;
    const float M1 = fdec(g_m1u), M2 = fdec(g_m2u);
    const float X = M1 + M2;
    const float L0 = (X >= 0.f) ? X : 0.5f * X;
    const float s1 = g_s1[i], s2 = g_s2[i];
    g_ar2[i] = make_float2(expf(s1 - M1), expf(0.5f * (s1 - M1)));
    g_ep2[i] = make_float2(expf(s2 - (L0 - M1)), expf(0.5f * s2 - L0 + 0.5f * M1));
}

// ================= K4: fused weights + fp16 mma, B staged in smem =================
#define LOAD_HALF(AW1, AW2, EP, HH) do {                                          \
    const int _j0 = jbase + (HH) * 32;                                            \
    AW1 = g_adjT[(size_t)(wb0 + (HH)) * N + r1];                                  \
    AW2 = g_adjT[(size_t)(wb0 + (HH)) * N + r2];                                  \
    _Pragma("unroll")                                                             \
    for (int _kb = 0; _kb < 2; _kb++)                                             \
        _Pragma("unroll")                                                         \
        for (int _pr = 0; _pr < 2; _pr++)                                         \
            EP[_kb][_pr] = *reinterpret_cast<const float4*>(                      \
                &g_ep2[_j0 + _kb * 16 + 2 * tq + _pr * 8]);                       \
} while (0)

__global__ __launch_bounds__(256, 2) void gat_mma() {
    __shared__ __align__(16) uint4 smB[3 * 512];      // 3 x 8KB B-fragment buffers

    const int t = threadIdx.x;
    const int w = t >> 5, lane = t & 31;
    const int g = lane >> 2, tq = lane & 3;
    const int split = blockIdx.x;
    const int rowbase = blockIdx.y * TIROWS;
    const int jbase = split * JSPAN;
    const int kbg0 = jbase >> 4;
    const int wb0 = jbase >> 5;

    const int r1 = rowbase + w * 16 + g;
    const int r2 = r1 + 8;
    const float2 ar1 = g_ar2[r1];
    const float2 ar2v = g_ar2[r2];

    float acc[8][4];
    #pragma unroll
    for (int nt = 0; nt < 8; nt++)
        #pragma unroll
        for (int c = 0; c < 4; c++) acc[nt][c] = 0.f;
    float Z1 = 0.f, Z2 = 0.f;

    // adj/ep register double-buffer (2-half granularity)
    unsigned aw1_0, aw2_0, aw1_1, aw2_1;
    float4 ep0[2][2], ep1[2][2];
    LOAD_HALF(aw1_0, aw2_0, ep0, 0);
    LOAD_HALF(aw1_1, aw2_1, ep1, 1);

    // B staging: half h occupies 512 uint4 at bsrc + h*512
    const uint4* bsrc = g_Bfrag + (size_t)kbg0 * 256;
    uint4 pA = bsrc[t], pB = bsrc[256 + t];           // half 0
    smB[t] = pA; smB[256 + t] = pB;                   // store buf 0
    pA = bsrc[512 + t]; pB = bsrc[768 + t];           // prefetch half 1

    for (int h = 0; h < NH; h++) {
        // store half h+1 into buf (h+1)%3, prefetch half h+2
        if (h + 1 < NH) {
            const int nb = ((h + 1) % 3) * 512;
            smB[nb + t] = pA; smB[nb + 256 + t] = pB;
        }
        if (h + 2 < NH) {
            pA = bsrc[(size_t)(h + 2) * 512 + t];
            pB = bsrc[(size_t)(h + 2) * 512 + 256 + t];
        }
        __syncthreads();

        const unsigned aw1 = (h & 1) ? aw1_1 : aw1_0;
        const unsigned aw2 = (h & 1) ? aw2_1 : aw2_0;
        const uint4* bs = smB + (h % 3) * 512 + lane;

        #pragma unroll
        for (int kb = 0; kb < 2; kb++) {
            uint32_t ahi[4];
            #pragma unroll
            for (int pr = 0; pr < 2; pr++) {
                const float4 e = (h & 1) ? ep1[kb][pr] : ep0[kb][pr];
                const int jloc = kb * 16 + 2 * tq + pr * 8;
                const float w1a = ((aw1 >> jloc) & 1u) ? fmaxf(ar1.x * e.x, ar1.y * e.y) : 0.f;
                const float w1b = ((aw1 >> (jloc + 1)) & 1u) ? fmaxf(ar1.x * e.z, ar1.y * e.w) : 0.f;
                const float w2a = ((aw2 >> jloc) & 1u) ? fmaxf(ar2v.x * e.x, ar2v.y * e.y) : 0.f;
                const float w2b = ((aw2 >> (jloc + 1)) & 1u) ? fmaxf(ar2v.x * e.z, ar2v.y * e.w) : 0.f;
                Z1 += w1a + w1b;
                Z2 += w2a + w2b;
                ahi[2 * pr + 0] = f16x2_pack(w1a, w1b);
                ahi[2 * pr + 1] = f16x2_pack(w2a, w2b);
            }
            #pragma unroll
            for (int nt = 0; nt < 8; nt++) {
                const uint4 b = bs[(kb * 8 + nt) * 32];
                MMA16816(acc[nt], ahi[0], ahi[1], ahi[2], ahi[3], b.x, b.y);
                MMA16816(acc[nt], ahi[0], ahi[1], ahi[2], ahi[3], b.z, b.w);
            }
        }

        // refill adj/ep buffer just consumed (2 halves ahead)
        if ((h & 1) == 0) { if (h + 2 < NH) LOAD_HALF(aw1_0, aw2_0, ep0, h + 2); }
        else              { if (h + 2 < NH) LOAD_HALF(aw1_1, aw2_1, ep1, h + 2); }
    }

    // Z reduce across the t-quad
    Z1 += __shfl_xor_sync(0xffffffffu, Z1, 1);
    Z1 += __shfl_xor_sync(0xffffffffu, Z1, 2);
    Z2 += __shfl_xor_sync(0xffffffffu, Z2, 1);
    Z2 += __shfl_xor_sync(0xffffffffu, Z2, 2);
    if (tq == 0) {
        g_Zp[split * N + r1] = Z1;
        g_Zp[split * N + r2] = Z2;
    }

    // store partial tile
    float* p1 = g_part + ((size_t)split * N + r1) * 64;
    float* p2 = g_part + ((size_t)split * N + r2) * 64;
    #pragma unroll
    for (int nt = 0; nt < 8; nt++) {
        const int c = nt * 8 + 2 * tq;
        *reinterpret_cast<float2*>(p1 + c) = make_float2(acc[nt][0], acc[nt][1]);
        *reinterpret_cast<float2*>(p2 + c) = make_float2(acc[nt][2], acc[nt][3]);
    }
}

// ================= K5: combine splits, normalize, relu =================
__global__ __launch_bounds__(256) void final_kernel(float* __restrict__ out) {
    const int idx = blockIdx.x * 256 + threadIdx.x;   // 8192*16 float4s
    const int row = idx >> 4;
    const int c4 = idx & 15;
    const float z = g_Zp[row] + g_Zp[N + row] + g_Zp[2 * N + row] + g_Zp[3 * N + row];
    const float inv = 1.f / z;
    const size_t off = (size_t)row * 64 + c4 * 4;
    float4 s = *reinterpret_cast<const float4*>(g_part + off);
    #pragma unroll
    for (int sp = 1; sp < NSPLIT; sp++) {
        const float4 p = *reinterpret_cast<const float4*>(g_part + (size_t)sp * N * 64 + off);
        s.x += p.x; s.y += p.y; s.z += p.z; s.w += p.w;
    }
    *reinterpret_cast<float4*>(out + off) = make_float4(
        fmaxf(s.x * inv, 0.f), fmaxf(s.y * inv, 0.f),
        fmaxf(s.z * inv, 0.f), fmaxf(s.w * inv, 0.f));
}

// ================= launch =================
extern "C" void kernel_launch(void* const* d_in, const int* in_sizes, int n_in,
                              void* d_out, int out_size) {
    const float* h   = (const float*)d_in[0];
    const int*   adj = (const int*)d_in[1];
    const float* W   = (const float*)d_in[2];
    const float* a   = (const float*)d_in[3];
    float*       out = (float*)d_out;

    fused0_kernel<<<WH_BLOCKS + BP_BLOCKS, 256>>>(h, W, adj);
    s_kernel<<<N / 8, 256>>>(a);
    epack_kernel<<<N / 128, 128>>>();
    gat_mma<<<dim3(NSPLIT, N / TIROWS), 256>>>();
    final_kernel<<<(N * 16) / 256, 256>>>(out);
}

// round 10
// speedup vs baseline: 2.6245x; 1.1629x over previous
#include <cuda_runtime.h>
#include <cuda_fp16.h>
#include <math.h>
#include <stdint.h>

#define N      8192
#define INCH   256
#define OUTCH  64
#define NSPLIT 4
#define JSPAN  (N / NSPLIT)     // 2048
#define TIROWS 128
#define NH     (JSPAN / 32)     // 64 halves (32 j each)
#define ONES16 0x3C003C00u

// ---------------- device scratch ----------------
__device__ float    g_Wh[N * OUTCH];
__device__ float    g_s1[N], g_s2[N];
__device__ unsigned g_m2u;                        // encoded float max (idempotent)
__device__ uint2    g_arh[N];                     // per-row (A1 h2, Ah h2) broadcast
__device__ uint2    g_eph[N / 2];                 // per j-pair (E1 h2, Eh h2)
__device__ unsigned g_adjT[(N / 32) * N];         // bit-packed adj [word][row]
// B in mma-fragment layout: [kbg][nt 0..7][lane 0..31] x uint2(b0,b1) fp16x2
__device__ uint2    g_Bfrag[(N / 16) * 8 * 32];
__device__ float    g_part[NSPLIT * N * OUTCH];
__device__ float    g_Zp[NSPLIT * N];

__device__ __forceinline__ unsigned fenc(float f) {
    unsigned u = __float_as_uint(f);
    return (u & 0x80000000u) ? ~u : (u | 0x80000000u);
}
__device__ __forceinline__ float fdec(unsigned k) {
    return __uint_as_float((k & 0x80000000u) ? (k ^ 0x80000000u) : ~k);
}
__device__ __forceinline__ uint32_t f16x2_pack(float lo, float hi) {
    uint32_t r;
    asm("cvt.rn.f16x2.f32 %0, %1, %2;" : "=r"(r) : "f"(hi), "f"(lo));
    return r;
}
__device__ __forceinline__ uint32_t hmul2(uint32_t a, uint32_t b) {
    uint32_t d;
    asm("mul.f16x2 %0, %1, %2;" : "=r"(d) : "r"(a), "r"(b));
    return d;
}
__device__ __forceinline__ uint32_t hmax2(uint32_t a, uint32_t b) {
    uint32_t d;
    asm("max.f16x2 %0, %1, %2;" : "=r"(d) : "r"(a), "r"(b));
    return d;
}
__device__ __forceinline__ uint32_t mk_mask(unsigned aw, int jloc) {
    uint32_t m = ((aw >> jloc) & 1u) ? 0x0000FFFFu : 0u;
    return m | (((aw >> (jloc + 1)) & 1u) ? 0xFFFF0000u : 0u);
}

#define MMA16816(d, a0, a1, a2, a3, b0, b1)                                       \
    asm volatile("mma.sync.aligned.m16n8k16.row.col.f32.f16.f16.f32 "            \
        "{%0,%1,%2,%3}, {%4,%5,%6,%7}, {%8,%9}, {%0,%1,%2,%3};"                  \
        : "+f"((d)[0]), "+f"((d)[1]), "+f"((d)[2]), "+f"((d)[3])                  \
        : "r"(a0), "r"(a1), "r"(a2), "r"(a3), "r"(b0), "r"(b1))

// ================= K0: fused wh-GEMM (blocks 0..511) + adj bitpack (rest) ======
#define WH_BLOCKS   (N / 16)          // 512
#define BP_BLOCKS   (8 * (N / 8))     // 8192

__global__ __launch_bounds__(256) void fused0_kernel(const float* __restrict__ h,
                                                     const float* __restrict__ W,
                                                     const int* __restrict__ adj) {
    __shared__ __align__(16) char smraw[64 * 64 * 4];
    const int t = threadIdx.x;
    const int bid = blockIdx.x;

    if (bid < WH_BLOCKS) {
        float* Ws = reinterpret_cast<float*>(smraw);
        const int col = t & 63;
        const int rowgrp = t >> 6;
        const int i0 = bid * 16;

        float acc[4] = {0.f, 0.f, 0.f, 0.f};
        for (int kc = 0; kc < 4; kc++) {
            __syncthreads();
            float4* wsv = reinterpret_cast<float4*>(Ws);
            const float4* wgv = reinterpret_cast<const float4*>(W + kc * 64 * 64);
            #pragma unroll
            for (int q = 0; q < 4; q++) wsv[t + 256 * q] = wgv[t + 256 * q];
            __syncthreads();

            #pragma unroll 4
            for (int kk = 0; kk < 64; kk += 4) {
                const int k = kc * 64 + kk;
                const float w0 = Ws[(kk + 0) * 64 + col];
                const float w1 = Ws[(kk + 1) * 64 + col];
                const float w2 = Ws[(kk + 2) * 64 + col];
                const float w3 = Ws[(kk + 3) * 64 + col];
                #pragma unroll
                for (int rr = 0; rr < 4; rr++) {
                    const int rrow = i0 + rowgrp * 4 + rr;
                    const float4 hv = *reinterpret_cast<const float4*>(h + (size_t)rrow * INCH + k);
                    acc[rr] += hv.x * w0 + hv.y * w1 + hv.z * w2 + hv.w * w3;
                }
            }
        }
        #pragma unroll
        for (int rr = 0; rr < 4; rr++)
            g_Wh[(size_t)(i0 + rowgrp * 4 + rr) * OUTCH + col] = acc[rr];

        // B fragment (single fp16), k = row index, n = col
        const int kbg = i0 >> 4;
        const int nt = col >> 3;
        const int g = col & 7;
        uint32_t* bf = reinterpret_cast<uint32_t*>(g_Bfrag);
        #pragma unroll
        for (int p = 0; p < 2; p++) {
            const int kp = rowgrp * 4 + 2 * p;
            const int slotbase = (kp < 8) ? 0 : 1;
            const int tq = (kp < 8) ? (kp >> 1) : ((kp - 8) >> 1);
            const int lane = g * 4 + tq;
            const uint32_t hw = f16x2_pack(acc[2 * p], acc[2 * p + 1]);
            bf[(((size_t)(kbg * 8 + nt) * 32 + lane) << 1) + slotbase] = hw;
        }
    } else {
        unsigned* sw = reinterpret_cast<unsigned*>(smraw);   // [32 words][9]
        const int b = bid - WH_BLOCKS;
        const int bx = b & 7;
        const int ry = b >> 3;
        const int wi = t >> 5, lane = t & 31;
        const int r = ry * 8 + wi;
        const int* rowp = adj + (size_t)r * N + (size_t)bx * 1024;
        #pragma unroll
        for (int ww = 0; ww < 32; ww++) {
            const int v = rowp[ww * 32 + lane];
            const unsigned word = __ballot_sync(0xffffffffu, v != 0);
            if (lane == 0) sw[ww * 9 + wi] = word;
        }
        __syncthreads();
        const int word = t >> 3, row = t & 7;
        g_adjT[(size_t)(bx * 32 + word) * N + ry * 8 + row] = sw[word * 9 + row];
    }
}

// ================= K2: s1/s2 + encoded global max of s2 =================
__global__ __launch_bounds__(256) void s_kernel(const float* __restrict__ a) {
    __shared__ float sm2[8];
    const int wid = threadIdx.x >> 5;
    const int lane = threadIdx.x & 31;
    const int i = blockIdx.x * 8 + wid;
    const float v1 = g_Wh[(size_t)i * 64 + lane];
    const float v2 = g_Wh[(size_t)i * 64 + 32 + lane];
    float p1 = v1 * a[lane] + v2 * a[32 + lane];
    float p2 = v1 * a[64 + lane] + v2 * a[96 + lane];
    #pragma unroll
    for (int o = 16; o; o >>= 1) {
        p1 += __shfl_xor_sync(0xffffffffu, p1, o);
        p2 += __shfl_xor_sync(0xffffffffu, p2, o);
    }
    if (lane == 0) { g_s1[i] = p1; g_s2[i] = p2; sm2[wid] = p2; }
    __syncthreads();
    if (threadIdx.x == 0) {
        float m2 = sm2[0];
        #pragma unroll
        for (int q = 1; q < 8; q++) m2 = fmaxf(m2, sm2[q]);
        atomicMax(&g_m2u, fenc(m2));
    }
}

// ================= K3: per-node half2 factors (per-row normalized) =============
// w_ij = exp(lrelu(s1_i+s2_j) - Lrow_i), Lrow_i = lrelu(s1_i + M2) >= all row logits
//      = max(A1_i*E1_j, Ah_i*Eh_j); all factors in (0,1].
__global__ __launch_bounds__(256) void epack_kernel() {
    const int i = blockIdx.x * 256 + threadIdx.x;
    const float M2 = fdec(g_m2u);
    if (i < N) {
        const float X = g_s1[i] + M2;
        const float Lrow = (X >= 0.f) ? X : 0.5f * X;
        const float A1 = expf(X - Lrow);
        const float Ah = expf(0.5f * X - Lrow);
        g_arh[i] = make_uint2(f16x2_pack(A1, A1), f16x2_pack(Ah, Ah));
    }
    if (i < N / 2) {
        const float s2a = g_s2[2 * i] - M2, s2b = g_s2[2 * i + 1] - M2;
        g_eph[i] = make_uint2(f16x2_pack(expf(s2a), expf(s2b)),
                              f16x2_pack(expf(0.5f * s2a), expf(0.5f * s2b)));
    }
}

// ================= K4: half2 weight-gen + fp16 mma, B+ep staged in smem ========
__global__ __launch_bounds__(256, 2) void gat_mma() {
    __shared__ __align__(16) uint2 smB[3 * 512];      // 3 x 4KB B buffers
    __shared__ __align__(8)  uint2 smE[3 * 16];       // 3 x 128B ep buffers

    const int t = threadIdx.x;
    const int w = t >> 5, lane = t & 31;
    const int g = lane >> 2, tq = lane & 3;
    const int split = blockIdx.x;
    const int rowbase = blockIdx.y * TIROWS;
    const int jbase = split * JSPAN;
    const int kbg0 = jbase >> 4;
    const int wb0 = jbase >> 5;

    const int r1 = rowbase + w * 16 + g;
    const int r2 = r1 + 8;
    const uint2 ar1 = g_arh[r1];
    const uint2 ar2 = g_arh[r2];

    float acc[8][4];
    #pragma unroll
    for (int nt = 0; nt < 8; nt++)
        #pragma unroll
        for (int c = 0; c < 4; c++) acc[nt][c] = 0.f;
    float accz[4] = {0.f, 0.f, 0.f, 0.f};

    unsigned aw1_0 = g_adjT[(size_t)wb0 * N + r1];
    unsigned aw2_0 = g_adjT[(size_t)wb0 * N + r2];
    unsigned aw1_1 = g_adjT[(size_t)(wb0 + 1) * N + r1];
    unsigned aw2_1 = g_adjT[(size_t)(wb0 + 1) * N + r2];

    const uint2* bsrc = g_Bfrag + (size_t)kbg0 * 256;   // 512 uint2 per half
    const uint2* esrc = g_eph + jbase / 2;              // 16 uint2 per half
    uint2 pA0 = bsrc[t], pA1 = bsrc[256 + t];
    uint2 pE;
    if (t < 16) pE = esrc[t];
    smB[t] = pA0; smB[256 + t] = pA1;
    if (t < 16) smE[t] = pE;
    pA0 = bsrc[512 + t]; pA1 = bsrc[768 + t];
    if (t < 16) pE = esrc[16 + t];

    for (int h = 0; h < NH; h++) {
        if (h + 1 < NH) {
            const int nb = (h + 1) % 3;
            smB[nb * 512 + t] = pA0;
            smB[nb * 512 + 256 + t] = pA1;
            if (t < 16) smE[nb * 16 + t] = pE;
        }
        if (h + 2 < NH) {
            pA0 = bsrc[(size_t)(h + 2) * 512 + t];
            pA1 = bsrc[(size_t)(h + 2) * 512 + 256 + t];
            if (t < 16) pE = esrc[(h + 2) * 16 + t];
        }
        __syncthreads();

        const unsigned aw1 = (h & 1) ? aw1_1 : aw1_0;
        const unsigned aw2 = (h & 1) ? aw2_1 : aw2_0;
        const uint2* bs = smB + (h % 3) * 512;
        const uint2* es = smE + (h % 3) * 16;

        #pragma unroll
        for (int kb = 0; kb < 2; kb++) {
            uint32_t av[4];
            #pragma unroll
            for (int pr = 0; pr < 2; pr++) {
                const int jloc = kb * 16 + pr * 8 + 2 * tq;
                const uint2 e = es[kb * 8 + pr * 4 + tq];
                const uint32_t w1 = hmax2(hmul2(ar1.x, e.x), hmul2(ar1.y, e.y));
                const uint32_t w2 = hmax2(hmul2(ar2.x, e.x), hmul2(ar2.y, e.y));
                av[2 * pr + 0] = w1 & mk_mask(aw1, jloc);
                av[2 * pr + 1] = w2 & mk_mask(aw2, jloc);
            }
            #pragma unroll
            for (int nt = 0; nt < 8; nt++) {
                const uint2 b = bs[(kb * 8 + nt) * 32 + lane];
                MMA16816(acc[nt], av[0], av[1], av[2], av[3], b.x, b.y);
            }
            MMA16816(accz, av[0], av[1], av[2], av[3], ONES16, ONES16);
        }

        // refill adj regs (2 halves ahead)
        if ((h & 1) == 0) {
            if (h + 2 < NH) {
                aw1_0 = g_adjT[(size_t)(wb0 + h + 2) * N + r1];
                aw2_0 = g_adjT[(size_t)(wb0 + h + 2) * N + r2];
            }
        } else if (h + 2 < NH) {
            aw1_1 = g_adjT[(size_t)(wb0 + h + 2) * N + r1];
            aw2_1 = g_adjT[(size_t)(wb0 + h + 2) * N + r2];
        }
    }

    // Z comes straight out of the ones-column accumulator (exact row sums)
    if (tq == 0) {
        g_Zp[split * N + r1] = accz[0];
        g_Zp[split * N + r2] = accz[2];
    }

    float* p1 = g_part + ((size_t)split * N + r1) * 64;
    float* p2 = g_part + ((size_t)split * N + r2) * 64;
    #pragma unroll
    for (int nt = 0; nt < 8; nt++) {
        const int c = nt * 8 + 2 * tq;
        *reinterpret_cast<float2*>(p1 + c) = make_float2(acc[nt][0], acc[nt][1]);
        *reinterpret_cast<float2*>(p2 + c) = make_float2(acc[nt][2], acc[nt][3]);
    }
}

// ================= K5: combine splits, normalize, relu =================
__global__ __launch_bounds__(256) void final_kernel(float* __restrict__ out) {
    const int idx = blockIdx.x * 256 + threadIdx.x;   // 8192*16 float4s
    const int row = idx >> 4;
    const int c4 = idx & 15;
    const float z = g_Zp[row] + g_Zp[N + row] + g_Zp[2 * N + row] + g_Zp[3 * N + row];
    const float inv = 1.f / z;
    const size_t off = (size_t)row * 64 + c4 * 4;
    float4 s = *reinterpret_cast<const float4*>(g_part + off);
    #pragma unroll
    for (int sp = 1; sp < NSPLIT; sp++) {
        const float4 p = *reinterpret_cast<const float4*>(g_part + (size_t)sp * N * 64 + off);
        s.x += p.x; s.y += p.y; s.z += p.z; s.w += p.w;
    }
    *reinterpret_cast<float4*>(out + off) = make_float4(
        fmaxf(s.x * inv, 0.f), fmaxf(s.y * inv, 0.f),
        fmaxf(s.z * inv, 0.f), fmaxf(s.w * inv, 0.f));
}

// ================= launch =================
extern "C" void kernel_launch(void* const* d_in, const int* in_sizes, int n_in,
                              void* d_out, int out_size) {
    const float* h   = (const float*)d_in[0];
    const int*   adj = (const int*)d_in[1];
    const float* W   = (const float*)d_in[2];
    const float* a   = (const float*)d_in[3];
    float*       out = (float*)d_out;

    fused0_kernel<<<WH_BLOCKS + BP_BLOCKS, 256>>>(h, W, adj);
    s_kernel<<<N / 8, 256>>>(a);
    epack_kernel<<<N / 256, 256>>>();
    gat_mma<<<dim3(NSPLIT, N / TIROWS), 256>>>();
    final_kernel<<<(N * 16) / 256, 256>>>(out);
}

// round 11
// speedup vs baseline: 2.9337x; 1.1178x over previous
#include <cuda_runtime.h>
#include <cuda_fp16.h>
#include <math.h>
#include <stdint.h>

#define N      8192
#define INCH   256
#define OUTCH  64
#define NSPLIT 4
#define JSPAN  (N / NSPLIT)     // 2048
#define TIROWS 128
#define NH     (JSPAN / 32)     // 64 halves (32 j each)
#define ONES16 0x3C003C00u
#define STAGES 4

// ---------------- device scratch ----------------
__device__ float    g_Wh[N * OUTCH];
__device__ float    g_s1[N], g_s2[N];
__device__ unsigned g_m2u;                        // encoded float max (idempotent)
__device__ __align__(16) uint2 g_arh[N];          // per-row (A1 h2, Ah h2) broadcast
__device__ __align__(16) uint2 g_eph[N / 2];      // per j-pair (E1 h2, Eh h2)
__device__ unsigned g_adjT[(N / 32) * N];         // bit-packed adj [word][row]
// B in mma-fragment layout: [kbg][nt 0..7][lane 0..31] x uint2(b0,b1) fp16x2
__device__ __align__(16) uint2 g_Bfrag[(N / 16) * 8 * 32];
__device__ float    g_part[NSPLIT * N * OUTCH];
__device__ float    g_Zp[NSPLIT * N];

__device__ __forceinline__ unsigned fenc(float f) {
    unsigned u = __float_as_uint(f);
    return (u & 0x80000000u) ? ~u : (u | 0x80000000u);
}
__device__ __forceinline__ float fdec(unsigned k) {
    return __uint_as_float((k & 0x80000000u) ? (k ^ 0x80000000u) : ~k);
}
__device__ __forceinline__ uint32_t f16x2_pack(float lo, float hi) {
    uint32_t r;
    asm("cvt.rn.f16x2.f32 %0, %1, %2;" : "=r"(r) : "f"(hi), "f"(lo));
    return r;
}
__device__ __forceinline__ uint32_t hmul2(uint32_t a, uint32_t b) {
    uint32_t d;
    asm("mul.f16x2 %0, %1, %2;" : "=r"(d) : "r"(a), "r"(b));
    return d;
}
__device__ __forceinline__ uint32_t hmax2(uint32_t a, uint32_t b) {
    uint32_t d;
    asm("max.f16x2 %0, %1, %2;" : "=r"(d) : "r"(a), "r"(b));
    return d;
}
__device__ __forceinline__ uint32_t mk_mask(unsigned aw, int jloc) {
    uint32_t m = ((aw >> jloc) & 1u) ? 0x0000FFFFu : 0u;
    return m | (((aw >> (jloc + 1)) & 1u) ? 0xFFFF0000u : 0u);
}
__device__ __forceinline__ uint32_t smem_u32(const void* p) {
    uint32_t a;
    asm("{ .reg .u64 t; cvta.to.shared.u64 t, %1; cvt.u32.u64 %0, t; }" : "=r"(a) : "l"(p));
    return a;
}

#define MMA16816(d, a0, a1, a2, a3, b0, b1)                                       \
    asm volatile("mma.sync.aligned.m16n8k16.row.col.f32.f16.f16.f32 "            \
        "{%0,%1,%2,%3}, {%4,%5,%6,%7}, {%8,%9}, {%0,%1,%2,%3};"                  \
        : "+f"((d)[0]), "+f"((d)[1]), "+f"((d)[2]), "+f"((d)[3])                  \
        : "r"(a0), "r"(a1), "r"(a2), "r"(a3), "r"(b0), "r"(b1))

#define CP16(dst, src) \
    asm volatile("cp.async.cg.shared.global [%0], [%1], 16;" :: "r"(dst), "l"(src) : "memory")
#define CP_COMMIT()   asm volatile("cp.async.commit_group;" ::: "memory")
#define CP_WAIT(nn)   asm volatile("cp.async.wait_group %0;" :: "n"(nn) : "memory")

// ================= K0: fused wh-GEMM (blocks 0..511) + adj bitpack (rest) ======
#define WH_BLOCKS   (N / 16)          // 512
#define BP_BLOCKS   (8 * (N / 8))     // 8192

__global__ __launch_bounds__(256) void fused0_kernel(const float* __restrict__ h,
                                                     const float* __restrict__ W,
                                                     const int* __restrict__ adj) {
    __shared__ __align__(16) char smraw[64 * 64 * 4];
    const int t = threadIdx.x;
    const int bid = blockIdx.x;

    if (bid < WH_BLOCKS) {
        float* Ws = reinterpret_cast<float*>(smraw);
        const int col = t & 63;
        const int rowgrp = t >> 6;
        const int i0 = bid * 16;

        float acc[4] = {0.f, 0.f, 0.f, 0.f};
        for (int kc = 0; kc < 4; kc++) {
            __syncthreads();
            float4* wsv = reinterpret_cast<float4*>(Ws);
            const float4* wgv = reinterpret_cast<const float4*>(W + kc * 64 * 64);
            #pragma unroll
            for (int q = 0; q < 4; q++) wsv[t + 256 * q] = wgv[t + 256 * q];
            __syncthreads();

            #pragma unroll 4
            for (int kk = 0; kk < 64; kk += 4) {
                const int k = kc * 64 + kk;
                const float w0 = Ws[(kk + 0) * 64 + col];
                const float w1 = Ws[(kk + 1) * 64 + col];
                const float w2 = Ws[(kk + 2) * 64 + col];
                const float w3 = Ws[(kk + 3) * 64 + col];
                #pragma unroll
                for (int rr = 0; rr < 4; rr++) {
                    const int rrow = i0 + rowgrp * 4 + rr;
                    const float4 hv = *reinterpret_cast<const float4*>(h + (size_t)rrow * INCH + k);
                    acc[rr] += hv.x * w0 + hv.y * w1 + hv.z * w2 + hv.w * w3;
                }
            }
        }
        #pragma unroll
        for (int rr = 0; rr < 4; rr++)
            g_Wh[(size_t)(i0 + rowgrp * 4 + rr) * OUTCH + col] = acc[rr];

        // B fragment (single fp16), k = row index, n = col
        const int kbg = i0 >> 4;
        const int nt = col >> 3;
        const int g = col & 7;
        uint32_t* bf = reinterpret_cast<uint32_t*>(g_Bfrag);
        #pragma unroll
        for (int p = 0; p < 2; p++) {
            const int kp = rowgrp * 4 + 2 * p;
            const int slotbase = (kp < 8) ? 0 : 1;
            const int tq = (kp < 8) ? (kp >> 1) : ((kp - 8) >> 1);
            const int lane = g * 4 + tq;
            const uint32_t hw = f16x2_pack(acc[2 * p], acc[2 * p + 1]);
            bf[(((size_t)(kbg * 8 + nt) * 32 + lane) << 1) + slotbase] = hw;
        }
    } else {
        unsigned* sw = reinterpret_cast<unsigned*>(smraw);   // [32 words][9]
        const int b = bid - WH_BLOCKS;
        const int bx = b & 7;
        const int ry = b >> 3;
        const int wi = t >> 5, lane = t & 31;
        const int r = ry * 8 + wi;
        const int* rowp = adj + (size_t)r * N + (size_t)bx * 1024;
        #pragma unroll
        for (int ww = 0; ww < 32; ww++) {
            const int v = rowp[ww * 32 + lane];
            const unsigned word = __ballot_sync(0xffffffffu, v != 0);
            if (lane == 0) sw[ww * 9 + wi] = word;
        }
        __syncthreads();
        const int word = t >> 3, row = t & 7;
        g_adjT[(size_t)(bx * 32 + word) * N + ry * 8 + row] = sw[word * 9 + row];
    }
}

// ================= K2: s1/s2 + encoded global max of s2 =================
__global__ __launch_bounds__(256) void s_kernel(const float* __restrict__ a) {
    __shared__ float sm2[8];
    const int wid = threadIdx.x >> 5;
    const int lane = threadIdx.x & 31;
    const int i = blockIdx.x * 8 + wid;
    const float v1 = g_Wh[(size_t)i * 64 + lane];
    const float v2 = g_Wh[(size_t)i * 64 + 32 + lane];
    float p1 = v1 * a[lane] + v2 * a[32 + lane];
    float p2 = v1 * a[64 + lane] + v2 * a[96 + lane];
    #pragma unroll
    for (int o = 16; o; o >>= 1) {
        p1 += __shfl_xor_sync(0xffffffffu, p1, o);
        p2 += __shfl_xor_sync(0xffffffffu, p2, o);
    }
    if (lane == 0) { g_s1[i] = p1; g_s2[i] = p2; sm2[wid] = p2; }
    __syncthreads();
    if (threadIdx.x == 0) {
        float m2 = sm2[0];
        #pragma unroll
        for (int q = 1; q < 8; q++) m2 = fmaxf(m2, sm2[q]);
        atomicMax(&g_m2u, fenc(m2));
    }
}

// ================= K3: per-node half2 factors (per-row normalized) =============
__global__ __launch_bounds__(256) void epack_kernel() {
    const int i = blockIdx.x * 256 + threadIdx.x;
    const float M2 = fdec(g_m2u);
    if (i < N) {
        const float X = g_s1[i] + M2;
        const float Lrow = (X >= 0.f) ? X : 0.5f * X;
        const float A1 = expf(X - Lrow);
        const float Ah = expf(0.5f * X - Lrow);
        g_arh[i] = make_uint2(f16x2_pack(A1, A1), f16x2_pack(Ah, Ah));
    }
    if (i < N / 2) {
        const float s2a = g_s2[2 * i] - M2, s2b = g_s2[2 * i + 1] - M2;
        g_eph[i] = make_uint2(f16x2_pack(expf(s2a), expf(s2b)),
                              f16x2_pack(expf(0.5f * s2a), expf(0.5f * s2b)));
    }
}

// ================= K4: half2 weight-gen + fp16 mma, cp.async B/ep staging ======
__global__ __launch_bounds__(256, 2) void gat_mma() {
    __shared__ __align__(16) uint2 smB[STAGES * 512];   // 4 x 4KB B buffers
    __shared__ __align__(16) uint2 smE[STAGES * 16];    // 4 x 128B ep buffers

    const int t = threadIdx.x;
    const int w = t >> 5, lane = t & 31;
    const int g = lane >> 2, tq = lane & 3;
    const int split = blockIdx.x;
    const int rowbase = blockIdx.y * TIROWS;
    const int jbase = split * JSPAN;
    const int kbg0 = jbase >> 4;
    const int wb0 = jbase >> 5;

    const int r1 = rowbase + w * 16 + g;
    const int r2 = r1 + 8;
    const uint2 ar1 = g_arh[r1];
    const uint2 ar2 = g_arh[r2];

    float acc[8][4];
    #pragma unroll
    for (int nt = 0; nt < 8; nt++)
        #pragma unroll
        for (int c = 0; c < 4; c++) acc[nt][c] = 0.f;
    float accz[4] = {0.f, 0.f, 0.f, 0.f};

    unsigned aw1_0 = g_adjT[(size_t)wb0 * N + r1];
    unsigned aw2_0 = g_adjT[(size_t)wb0 * N + r2];
    unsigned aw1_1 = g_adjT[(size_t)(wb0 + 1) * N + r1];
    unsigned aw2_1 = g_adjT[(size_t)(wb0 + 1) * N + r2];

    // cp.async staging: per half, B = 256 uint4 (one per thread), ep = 8 uint4
    const uint4* bsrc4 = reinterpret_cast<const uint4*>(g_Bfrag + (size_t)kbg0 * 256);
    const uint4* esrc4 = reinterpret_cast<const uint4*>(g_eph + jbase / 2);
    const uint32_t sbB = smem_u32(smB);
    const uint32_t sbE = smem_u32(smE);

    #pragma unroll
    for (int s = 0; s < STAGES - 1; s++) {
        CP16(sbB + s * 4096 + t * 16, bsrc4 + (size_t)s * 256 + t);
        if (t < 8) CP16(sbE + s * 128 + t * 16, esrc4 + s * 8 + t);
        CP_COMMIT();
    }

    for (int h = 0; h < NH; h++) {
        const int slot = h % STAGES;
        CP_WAIT(STAGES - 2);
        __syncthreads();

        // issue stage h+STAGES-1 into the slot consumed at h-1 (all warps past it)
        if (h + STAGES - 1 < NH) {
            const int hs = h + STAGES - 1;
            const int ns = hs % STAGES;
            CP16(sbB + ns * 4096 + t * 16, bsrc4 + (size_t)hs * 256 + t);
            if (t < 8) CP16(sbE + ns * 128 + t * 16, esrc4 + hs * 8 + t);
        }
        CP_COMMIT();

        const unsigned aw1 = (h & 1) ? aw1_1 : aw1_0;
        const unsigned aw2 = (h & 1) ? aw2_1 : aw2_0;
        const uint2* bs = smB + slot * 512;
        const uint2* es = smE + slot * 16;

        // preload kb0's B fragments; latency hides under av generation
        uint2 bpre[8];
        #pragma unroll
        for (int nt = 0; nt < 8; nt++) bpre[nt] = bs[nt * 32 + lane];

        #pragma unroll
        for (int kb = 0; kb < 2; kb++) {
            uint32_t av[4];
            #pragma unroll
            for (int pr = 0; pr < 2; pr++) {
                const int jloc = kb * 16 + pr * 8 + 2 * tq;
                const uint2 e = es[kb * 8 + pr * 4 + tq];
                const uint32_t w1 = hmax2(hmul2(ar1.x, e.x), hmul2(ar1.y, e.y));
                const uint32_t w2 = hmax2(hmul2(ar2.x, e.x), hmul2(ar2.y, e.y));
                av[2 * pr + 0] = w1 & mk_mask(aw1, jloc);
                av[2 * pr + 1] = w2 & mk_mask(aw2, jloc);
            }
            #pragma unroll
            for (int nt = 0; nt < 8; nt++) {
                const uint2 b = kb ? bs[(8 + nt) * 32 + lane] : bpre[nt];
                MMA16816(acc[nt], av[0], av[1], av[2], av[3], b.x, b.y);
            }
            MMA16816(accz, av[0], av[1], av[2], av[3], ONES16, ONES16);
        }

        // refill adj regs (2 halves ahead)
        if ((h & 1) == 0) {
            if (h + 2 < NH) {
                aw1_0 = g_adjT[(size_t)(wb0 + h + 2) * N + r1];
                aw2_0 = g_adjT[(size_t)(wb0 + h + 2) * N + r2];
            }
        } else if (h + 2 < NH) {
            aw1_1 = g_adjT[(size_t)(wb0 + h + 2) * N + r1];
            aw2_1 = g_adjT[(size_t)(wb0 + h + 2) * N + r2];
        }
    }

    if (tq == 0) {
        g_Zp[split * N + r1] = accz[0];
        g_Zp[split * N + r2] = accz[2];
    }

    float* p1 = g_part + ((size_t)split * N + r1) * 64;
    float* p2 = g_part + ((size_t)split * N + r2) * 64;
    #pragma unroll
    for (int nt = 0; nt < 8; nt++) {
        const int c = nt * 8 + 2 * tq;
        *reinterpret_cast<float2*>(p1 + c) = make_float2(acc[nt][0], acc[nt][1]);
        *reinterpret_cast<float2*>(p2 + c) = make_float2(acc[nt][2], acc[nt][3]);
    }
}

// ================= K5: combine splits, normalize, relu =================
__global__ __launch_bounds__(256) void final_kernel(float* __restrict__ out) {
    const int idx = blockIdx.x * 256 + threadIdx.x;   // 8192*16 float4s
    const int row = idx >> 4;
    const int c4 = idx & 15;
    const float z = g_Zp[row] + g_Zp[N + row] + g_Zp[2 * N + row] + g_Zp[3 * N + row];
    const float inv = 1.f / z;
    const size_t off = (size_t)row * 64 + c4 * 4;
    float4 s = *reinterpret_cast<const float4*>(g_part + off);
    #pragma unroll
    for (int sp = 1; sp < NSPLIT; sp++) {
        const float4 p = *reinterpret_cast<const float4*>(g_part + (size_t)sp * N * 64 + off);
        s.x += p.x; s.y += p.y; s.z += p.z; s.w += p.w;
    }
    *reinterpret_cast<float4*>(out + off) = make_float4(
        fmaxf(s.x * inv, 0.f), fmaxf(s.y * inv, 0.f),
        fmaxf(s.z * inv, 0.f), fmaxf(s.w * inv, 0.f));
}

// ================= launch =================
extern "C" void kernel_launch(void* const* d_in, const int* in_sizes, int n_in,
                              void* d_out, int out_size) {
    const float* h   = (const float*)d_in[0];
    const int*   adj = (const int*)d_in[1];
    const float* W   = (const float*)d_in[2];
    const float* a   = (const float*)d_in[3];
    float*       out = (float*)d_out;

    fused0_kernel<<<WH_BLOCKS + BP_BLOCKS, 256>>>(h, W, adj);
    s_kernel<<<N / 8, 256>>>(a);
    epack_kernel<<<N / 256, 256>>>();
    gat_mma<<<dim3(NSPLIT, N / TIROWS), 256>>>();
    final_kernel<<<(N * 16) / 256, 256>>>(out);
}

// round 12
// speedup vs baseline: 3.1439x; 1.0717x over previous
#include <cuda_runtime.h>
#include <cuda_fp16.h>
#include <math.h>
#include <stdint.h>

#define N      8192
#define INCH   256
#define OUTCH  64
#define NSPLIT 4
#define JSPAN  (N / NSPLIT)     // 2048
#define TIROWS 128
#define NIT    (JSPAN / 64)     // 32 iterations (64 j each)
#define ONES16 0x3C003C00u
#define STAGES 3

// ---------------- device scratch ----------------
__device__ float    g_Wh[N * OUTCH];
__device__ float    g_s1[N], g_s2[N];
__device__ unsigned g_m2u;                        // encoded float max (idempotent)
__device__ __align__(16) uint2 g_arh[N];          // per-row (A1 h2, Ah h2) broadcast
__device__ __align__(16) uint2 g_eph[N / 2];      // per j-pair (E1 h2, Eh h2)
__device__ unsigned g_adjT[(N / 32) * N];         // bit-packed adj [word][row]
// B in mma-fragment layout: [kbg][nt 0..7][lane 0..31] x uint2(b0,b1) fp16x2
__device__ __align__(16) uint2 g_Bfrag[(N / 16) * 8 * 32];
__device__ float    g_part[NSPLIT * N * OUTCH];
__device__ float    g_Zp[NSPLIT * N];

__device__ __forceinline__ unsigned fenc(float f) {
    unsigned u = __float_as_uint(f);
    return (u & 0x80000000u) ? ~u : (u | 0x80000000u);
}
__device__ __forceinline__ float fdec(unsigned k) {
    return __uint_as_float((k & 0x80000000u) ? (k ^ 0x80000000u) : ~k);
}
__device__ __forceinline__ uint32_t f16x2_pack(float lo, float hi) {
    uint32_t r;
    asm("cvt.rn.f16x2.f32 %0, %1, %2;" : "=r"(r) : "f"(hi), "f"(lo));
    return r;
}
__device__ __forceinline__ uint32_t hmul2(uint32_t a, uint32_t b) {
    uint32_t d;
    asm("mul.f16x2 %0, %1, %2;" : "=r"(d) : "r"(a), "r"(b));
    return d;
}
__device__ __forceinline__ uint32_t hmax2(uint32_t a, uint32_t b) {
    uint32_t d;
    asm("max.f16x2 %0, %1, %2;" : "=r"(d) : "r"(a), "r"(b));
    return d;
}
// expand adjacency bit-pair (jloc, jloc+1) into two 16-bit lane masks via PRMT sign mode
__device__ __forceinline__ uint32_t mk_mask2(unsigned aw, int jloc) {
    const uint32_t y = (aw >> jloc) & 3u;
    const uint32_t x = y * 0x4080u;          // byte0 MSB = bit0, byte1 MSB = bit1
    uint32_t m;
    asm("prmt.b32 %0, %1, %2, 0x9988;" : "=r"(m) : "r"(x), "r"(0u));
    return m;
}
__device__ __forceinline__ uint32_t smem_u32(const void* p) {
    uint32_t a;
    asm("{ .reg .u64 t; cvta.to.shared.u64 t, %1; cvt.u32.u64 %0, t; }" : "=r"(a) : "l"(p));
    return a;
}

#define MMA16816(d, a0, a1, a2, a3, b0, b1)                                       \
    asm volatile("mma.sync.aligned.m16n8k16.row.col.f32.f16.f16.f32 "            \
        "{%0,%1,%2,%3}, {%4,%5,%6,%7}, {%8,%9}, {%0,%1,%2,%3};"                  \
        : "+f"((d)[0]), "+f"((d)[1]), "+f"((d)[2]), "+f"((d)[3])                  \
        : "r"(a0), "r"(a1), "r"(a2), "r"(a3), "r"(b0), "r"(b1))

#define CP16(dst, src) \
    asm volatile("cp.async.cg.shared.global [%0], [%1], 16;" :: "r"(dst), "l"(src) : "memory")
#define CP_COMMIT()   asm volatile("cp.async.commit_group;" ::: "memory")
#define CP_WAIT(nn)   asm volatile("cp.async.wait_group %0;" :: "n"(nn) : "memory")

// ================= K0: fused wh-GEMM (blocks 0..511) + adj bitpack (rest) ======
#define WH_BLOCKS   (N / 16)          // 512
#define BP_BLOCKS   (8 * (N / 8))     // 8192

__global__ __launch_bounds__(256) void fused0_kernel(const float* __restrict__ h,
                                                     const float* __restrict__ W,
                                                     const int* __restrict__ adj) {
    __shared__ __align__(16) char smraw[64 * 64 * 4];
    const int t = threadIdx.x;
    const int bid = blockIdx.x;

    if (bid < WH_BLOCKS) {
        float* Ws = reinterpret_cast<float*>(smraw);
        const int col = t & 63;
        const int rowgrp = t >> 6;
        const int i0 = bid * 16;

        float acc[4] = {0.f, 0.f, 0.f, 0.f};
        for (int kc = 0; kc < 4; kc++) {
            __syncthreads();
            float4* wsv = reinterpret_cast<float4*>(Ws);
            const float4* wgv = reinterpret_cast<const float4*>(W + kc * 64 * 64);
            #pragma unroll
            for (int q = 0; q < 4; q++) wsv[t + 256 * q] = wgv[t + 256 * q];
            __syncthreads();

            #pragma unroll 4
            for (int kk = 0; kk < 64; kk += 4) {
                const int k = kc * 64 + kk;
                const float w0 = Ws[(kk + 0) * 64 + col];
                const float w1 = Ws[(kk + 1) * 64 + col];
                const float w2 = Ws[(kk + 2) * 64 + col];
                const float w3 = Ws[(kk + 3) * 64 + col];
                #pragma unroll
                for (int rr = 0; rr < 4; rr++) {
                    const int rrow = i0 + rowgrp * 4 + rr;
                    const float4 hv = *reinterpret_cast<const float4*>(h + (size_t)rrow * INCH + k);
                    acc[rr] += hv.x * w0 + hv.y * w1 + hv.z * w2 + hv.w * w3;
                }
            }
        }
        #pragma unroll
        for (int rr = 0; rr < 4; rr++)
            g_Wh[(size_t)(i0 + rowgrp * 4 + rr) * OUTCH + col] = acc[rr];

        // B fragment (single fp16), k = row index, n = col
        const int kbg = i0 >> 4;
        const int nt = col >> 3;
        const int g = col & 7;
        uint32_t* bf = reinterpret_cast<uint32_t*>(g_Bfrag);
        #pragma unroll
        for (int p = 0; p < 2; p++) {
            const int kp = rowgrp * 4 + 2 * p;
            const int slotbase = (kp < 8) ? 0 : 1;
            const int tq = (kp < 8) ? (kp >> 1) : ((kp - 8) >> 1);
            const int lane = g * 4 + tq;
            const uint32_t hw = f16x2_pack(acc[2 * p], acc[2 * p + 1]);
            bf[(((size_t)(kbg * 8 + nt) * 32 + lane) << 1) + slotbase] = hw;
        }
    } else {
        unsigned* sw = reinterpret_cast<unsigned*>(smraw);   // [32 words][9]
        const int b = bid - WH_BLOCKS;
        const int bx = b & 7;
        const int ry = b >> 3;
        const int wi = t >> 5, lane = t & 31;
        const int r = ry * 8 + wi;
        const int* rowp = adj + (size_t)r * N + (size_t)bx * 1024;
        #pragma unroll
        for (int ww = 0; ww < 32; ww++) {
            const int v = rowp[ww * 32 + lane];
            const unsigned word = __ballot_sync(0xffffffffu, v != 0);
            if (lane == 0) sw[ww * 9 + wi] = word;
        }
        __syncthreads();
        const int word = t >> 3, row = t & 7;
        g_adjT[(size_t)(bx * 32 + word) * N + ry * 8 + row] = sw[word * 9 + row];
    }
}

// ================= K2: s1/s2 + encoded global max of s2 =================
__global__ __launch_bounds__(256) void s_kernel(const float* __restrict__ a) {
    __shared__ float sm2[8];
    const int wid = threadIdx.x >> 5;
    const int lane = threadIdx.x & 31;
    const int i = blockIdx.x * 8 + wid;
    const float v1 = g_Wh[(size_t)i * 64 + lane];
    const float v2 = g_Wh[(size_t)i * 64 + 32 + lane];
    float p1 = v1 * a[lane] + v2 * a[32 + lane];
    float p2 = v1 * a[64 + lane] + v2 * a[96 + lane];
    #pragma unroll
    for (int o = 16; o; o >>= 1) {
        p1 += __shfl_xor_sync(0xffffffffu, p1, o);
        p2 += __shfl_xor_sync(0xffffffffu, p2, o);
    }
    if (lane == 0) { g_s1[i] = p1; g_s2[i] = p2; sm2[wid] = p2; }
    __syncthreads();
    if (threadIdx.x == 0) {
        float m2 = sm2[0];
        #pragma unroll
        for (int q = 1; q < 8; q++) m2 = fmaxf(m2, sm2[q]);
        atomicMax(&g_m2u, fenc(m2));
    }
}

// ================= K3: per-node half2 factors (per-row normalized) =============
__global__ __launch_bounds__(256) void epack_kernel() {
    const int i = blockIdx.x * 256 + threadIdx.x;
    const float M2 = fdec(g_m2u);
    if (i < N) {
        const float X = g_s1[i] + M2;
        const float Lrow = (X >= 0.f) ? X : 0.5f * X;
        const float A1 = expf(X - Lrow);
        const float Ah = expf(0.5f * X - Lrow);
        g_arh[i] = make_uint2(f16x2_pack(A1, A1), f16x2_pack(Ah, Ah));
    }
    if (i < N / 2) {
        const float s2a = g_s2[2 * i] - M2, s2b = g_s2[2 * i + 1] - M2;
        g_eph[i] = make_uint2(f16x2_pack(expf(s2a), expf(s2b)),
                              f16x2_pack(expf(0.5f * s2a), expf(0.5f * s2b)));
    }
}

// ================= K4: half2 weight-gen + fp16 mma, 64-j stages =================
__global__ __launch_bounds__(256, 2) void gat_mma() {
    __shared__ __align__(16) uint2 smB[STAGES * 1024];   // 3 x 8KB B buffers
    __shared__ __align__(16) uint2 smE[STAGES * 32];     // 3 x 256B ep buffers

    const int t = threadIdx.x;
    const int w = t >> 5, lane = t & 31;
    const int g = lane >> 2, tq = lane & 3;
    const int split = blockIdx.x;
    const int rowbase = blockIdx.y * TIROWS;
    const int jbase = split * JSPAN;
    const int kbg0 = jbase >> 4;
    const int wb0 = jbase >> 5;

    const int r1 = rowbase + w * 16 + g;
    const int r2 = r1 + 8;
    const uint2 ar1 = g_arh[r1];
    const uint2 ar2 = g_arh[r2];

    float acc[8][4];
    #pragma unroll
    for (int nt = 0; nt < 8; nt++)
        #pragma unroll
        for (int c = 0; c < 4; c++) acc[nt][c] = 0.f;
    float accz[4] = {0.f, 0.f, 0.f, 0.f};

    // adj words: 2 per row per 64-j iteration; cur + next in regs
    unsigned c1a = g_adjT[(size_t)wb0 * N + r1];
    unsigned c1b = g_adjT[(size_t)(wb0 + 1) * N + r1];
    unsigned c2a = g_adjT[(size_t)wb0 * N + r2];
    unsigned c2b = g_adjT[(size_t)(wb0 + 1) * N + r2];

    const uint4* bsrc4 = reinterpret_cast<const uint4*>(g_Bfrag + (size_t)kbg0 * 256);
    const uint4* esrc4 = reinterpret_cast<const uint4*>(g_eph + jbase / 2);
    const uint32_t sbB = smem_u32(smB);
    const uint32_t sbE = smem_u32(smE);

    // prologue: stages 0,1
    #pragma unroll
    for (int s = 0; s < STAGES - 1; s++) {
        CP16(sbB + s * 8192 + t * 16, bsrc4 + (size_t)s * 512 + t);
        CP16(sbB + s * 8192 + 4096 + t * 16, bsrc4 + (size_t)s * 512 + 256 + t);
        if (t < 16) CP16(sbE + s * 256 + t * 16, esrc4 + s * 16 + t);
        CP_COMMIT();
    }

    for (int hh = 0; hh < NIT; hh++) {
        const int slot = hh % STAGES;
        CP_WAIT(1);
        __syncthreads();

        // issue stage hh+2 into slot consumed at hh-1
        if (hh + 2 < NIT) {
            const int hs = hh + 2;
            const int ns = hs % STAGES;
            CP16(sbB + ns * 8192 + t * 16, bsrc4 + (size_t)hs * 512 + t);
            CP16(sbB + ns * 8192 + 4096 + t * 16, bsrc4 + (size_t)hs * 512 + 256 + t);
            if (t < 16) CP16(sbE + ns * 256 + t * 16, esrc4 + hs * 16 + t);
        }
        CP_COMMIT();

        // prefetch next iteration's adj words
        unsigned n1a = 0, n1b = 0, n2a = 0, n2b = 0;
        if (hh + 1 < NIT) {
            const size_t wi = (size_t)(wb0 + 2 * (hh + 1)) * N;
            n1a = g_adjT[wi + r1];        n2a = g_adjT[wi + r2];
            n1b = g_adjT[wi + N + r1];    n2b = g_adjT[wi + N + r2];
        }

        const uint2* bs = smB + slot * 1024;
        const uint2* es = smE + slot * 32;

        // preload the first 8 B fragments; LDS latency hides under av gen
        uint2 bpre[8];
        #pragma unroll
        for (int nt = 0; nt < 8; nt++) bpre[nt] = bs[nt * 32 + lane];

        #pragma unroll
        for (int q = 0; q < 2; q++) {
            const unsigned aw1 = q ? c1b : c1a;
            const unsigned aw2 = q ? c2b : c2a;
            #pragma unroll
            for (int kb = 0; kb < 2; kb++) {
                uint32_t av[4];
                #pragma unroll
                for (int pr = 0; pr < 2; pr++) {
                    const int jloc = kb * 16 + pr * 8 + 2 * tq;
                    const uint2 e = es[q * 16 + kb * 8 + pr * 4 + tq];
                    const uint32_t w1 = hmax2(hmul2(ar1.x, e.x), hmul2(ar1.y, e.y));
                    const uint32_t w2 = hmax2(hmul2(ar2.x, e.x), hmul2(ar2.y, e.y));
                    av[2 * pr + 0] = w1 & mk_mask2(aw1, jloc);
                    av[2 * pr + 1] = w2 & mk_mask2(aw2, jloc);
                }
                #pragma unroll
                for (int nt = 0; nt < 8; nt++) {
                    const uint2 b = (q == 0 && kb == 0)
                                  ? bpre[nt]
                                  : bs[((q * 2 + kb) * 8 + nt) * 32 + lane];
                    MMA16816(acc[nt], av[0], av[1], av[2], av[3], b.x, b.y);
                }
                MMA16816(accz, av[0], av[1], av[2], av[3], ONES16, ONES16);
            }
        }

        c1a = n1a; c1b = n1b; c2a = n2a; c2b = n2b;
    }

    if (tq == 0) {
        g_Zp[split * N + r1] = accz[0];
        g_Zp[split * N + r2] = accz[2];
    }

    float* p1 = g_part + ((size_t)split * N + r1) * 64;
    float* p2 = g_part + ((size_t)split * N + r2) * 64;
    #pragma unroll
    for (int nt = 0; nt < 8; nt++) {
        const int c = nt * 8 + 2 * tq;
        *reinterpret_cast<float2*>(p1 + c) = make_float2(acc[nt][0], acc[nt][1]);
        *reinterpret_cast<float2*>(p2 + c) = make_float2(acc[nt][2], acc[nt][3]);
    }
}

// ================= K5: combine splits, normalize, relu =================
__global__ __launch_bounds__(256) void final_kernel(float* __restrict__ out) {
    const int idx = blockIdx.x * 256 + threadIdx.x;   // 8192*16 float4s
    const int row = idx >> 4;
    const int c4 = idx & 15;
    const float z = g_Zp[row] + g_Zp[N + row] + g_Zp[2 * N + row] + g_Zp[3 * N + row];
    const float inv = 1.f / z;
    const size_t off = (size_t)row * 64 + c4 * 4;
    float4 s = *reinterpret_cast<const float4*>(g_part + off);
    #pragma unroll
    for (int sp = 1; sp < NSPLIT; sp++) {
        const float4 p = *reinterpret_cast<const float4*>(g_part + (size_t)sp * N * 64 + off);
        s.x += p.x; s.y += p.y; s.z += p.z; s.w += p.w;
    }
    *reinterpret_cast<float4*>(out + off) = make_float4(
        fmaxf(s.x * inv, 0.f), fmaxf(s.y * inv, 0.f),
        fmaxf(s.z * inv, 0.f), fmaxf(s.w * inv, 0.f));
}

// ================= launch =================
extern "C" void kernel_launch(void* const* d_in, const int* in_sizes, int n_in,
                              void* d_out, int out_size) {
    const float* h   = (const float*)d_in[0];
    const int*   adj = (const int*)d_in[1];
    const float* W   = (const float*)d_in[2];
    const float* a   = (const float*)d_in[3];
    float*       out = (float*)d_out;

    fused0_kernel<<<WH_BLOCKS + BP_BLOCKS, 256>>>(h, W, adj);
    s_kernel<<<N / 8, 256>>>(a);
    epack_kernel<<<N / 256, 256>>>();
    gat_mma<<<dim3(NSPLIT, N / TIROWS), 256>>>();
    final_kernel<<<(N * 16) / 256, 256>>>(out);
}